// round 2
// baseline (speedup 1.0000x reference)
#include <cuda_runtime.h>
#include <math.h>

// Problem constants (fixed shapes)
#define BB 2
#define TT 2048
#define CC 1024
#define HH 16
#define HD 64
#define RR 8
#define DSTD 56

// Scratch (static device globals — no allocation)
__device__ float g_qkv[(size_t)BB * TT * 3 * CC];   // (B,T,3C)   48 MB
__device__ float g_qa[(size_t)BB * HH * TT * HD];   // (B,H,T,64) 16 MB
__device__ float g_ka[(size_t)BB * HH * TT * HD];   // (B,H,T,64) 16 MB
__device__ float g_ao[(size_t)BB * TT * CC];        // (B,T,C)    16 MB

// ---------------------------------------------------------------------------
// GEMM (NT): C[m,n] = sum_k A[m,k] * B[n,k]
// A: (M,K) row-major, B: (N,K) row-major. M,N % 128 == 0, K % 16 == 0.
// 128x128 tile, BK=16, 256 threads, 8x8 micro-tile per thread.
// ---------------------------------------------------------------------------
#define BM 128
#define BN 128
#define BK 16

__global__ __launch_bounds__(256) void gemm_nt(
    const float* __restrict__ A, const float* __restrict__ B,
    float* __restrict__ C, int M, int N, int K)
{
    __shared__ float As[BK][BM + 4];  // [k][m]
    __shared__ float Bs[BK][BN + 4];  // [k][n]

    const int bm = blockIdx.y * BM;
    const int bn = blockIdx.x * BN;
    const int tid = threadIdx.x;
    const int tx = tid & 15;          // 0..15  -> n
    const int ty = tid >> 4;          // 0..15  -> m

    float acc[8][8];
#pragma unroll
    for (int i = 0; i < 8; i++)
#pragma unroll
        for (int j = 0; j < 8; j++) acc[i][j] = 0.f;

    for (int k0 = 0; k0 < K; k0 += BK) {
        // Stage 128x16 tiles of A and B: 512 float4 each, 2 per thread.
#pragma unroll
        for (int it = 0; it < 2; it++) {
            int f = tid + it * 256;        // 0..511
            int row = f >> 2;              // 0..127
            int c4 = f & 3;                // 0..3
            float4 va = *(const float4*)(A + (size_t)(bm + row) * K + k0 + c4 * 4);
            As[c4 * 4 + 0][row] = va.x;
            As[c4 * 4 + 1][row] = va.y;
            As[c4 * 4 + 2][row] = va.z;
            As[c4 * 4 + 3][row] = va.w;
            float4 vb = *(const float4*)(B + (size_t)(bn + row) * K + k0 + c4 * 4);
            Bs[c4 * 4 + 0][row] = vb.x;
            Bs[c4 * 4 + 1][row] = vb.y;
            Bs[c4 * 4 + 2][row] = vb.z;
            Bs[c4 * 4 + 3][row] = vb.w;
        }
        __syncthreads();

#pragma unroll
        for (int k = 0; k < BK; k++) {
            float a_[8], b_[8];
            *(float4*)(a_ + 0) = *(const float4*)&As[k][ty * 8 + 0];
            *(float4*)(a_ + 4) = *(const float4*)&As[k][ty * 8 + 4];
            *(float4*)(b_ + 0) = *(const float4*)&Bs[k][tx * 8 + 0];
            *(float4*)(b_ + 4) = *(const float4*)&Bs[k][tx * 8 + 4];
#pragma unroll
            for (int i = 0; i < 8; i++)
#pragma unroll
                for (int j = 0; j < 8; j++) acc[i][j] += a_[i] * b_[j];
        }
        __syncthreads();
    }

#pragma unroll
    for (int i = 0; i < 8; i++) {
        float* crow = C + (size_t)(bm + ty * 8 + i) * N + bn + tx * 8;
        *(float4*)(crow + 0) = make_float4(acc[i][0], acc[i][1], acc[i][2], acc[i][3]);
        *(float4*)(crow + 4) = make_float4(acc[i][4], acc[i][5], acc[i][6], acc[i][7]);
    }
}

// ---------------------------------------------------------------------------
// Augmentation: for each (b,h,t) build
//   qa = [sqrt(w_std)*q[:56], sqrt(w_rec)*k_low]   (cross: q carries k_low)
//   ka = [sqrt(w_std)*k[:56], sqrt(w_rec)*q_low]
// One block per (b,h,t), 64 threads (one per dim).
// ---------------------------------------------------------------------------
__global__ __launch_bounds__(64) void augment_kernel(
    const float* __restrict__ qkv, float* __restrict__ qa, float* __restrict__ ka,
    const float* __restrict__ W_recip, const float* __restrict__ w_std,
    const float* __restrict__ w_rec)
{
    const int idx = blockIdx.x;            // (b*H + h)*T + t
    const int t = idx % TT;
    const int h = (idx / TT) % HH;
    const int b = idx / (TT * HH);

    const float* base = qkv + (size_t)(b * TT + t) * (3 * CC);
    const int d = threadIdx.x;             // 0..63

    float qd = base[h * HD + d];
    float kd = base[CC + h * HD + d];

    __shared__ float sq[HD], sk[HD], qlow[RR], klow[RR];
    sq[d] = qd;
    sk[d] = kd;
    __syncthreads();

    if (d < RR) {
        float s = 0.f;
#pragma unroll
        for (int i = 0; i < HD; i++) s += sq[i] * W_recip[i * RR + d];
        qlow[d] = s;
    } else if (d < 2 * RR) {
        int r = d - RR;
        float s = 0.f;
#pragma unroll
        for (int i = 0; i < HD; i++) s += sk[i] * W_recip[i * RR + r];
        klow[r] = s;
    }
    __syncthreads();

    const float sws = sqrtf(w_std[h]);
    const float swr = sqrtf(w_rec[h]);
    float qav = (d < DSTD) ? sws * qd : swr * klow[d - DSTD];
    float kav = (d < DSTD) ? sws * kd : swr * qlow[d - DSTD];

    size_t o = ((size_t)idx) * HD + d;
    qa[o] = qav;
    ka[o] = kav;
}

// ---------------------------------------------------------------------------
// Flash attention (causal) with per-head key bias.
// Grid: (T/128, B*H). 128 threads, one query row per thread.
// Key tiles of 64 (ka + v staged in smem). Output written in (B,T,H,64).
// ---------------------------------------------------------------------------
#define QB 128
#define KT 64

__global__ __launch_bounds__(128) void flash_kernel(
    const float* __restrict__ qa, const float* __restrict__ ka,
    const float* __restrict__ qkv, const float* __restrict__ d_bias,
    const float* __restrict__ w_disc, float* __restrict__ ao)
{
    const int bh = blockIdx.y;
    const int b = bh / HH;
    const int h = bh % HH;
    const int t0 = blockIdx.x * QB;
    const int tid = threadIdx.x;           // 0..127
    const int t = t0 + tid;                // this thread's query row

    __shared__ float skk[KT][HD];
    __shared__ float svv[KT][HD];
    __shared__ float sb[KT];

    // Load q_aug row into registers
    const float* qrow = qa + ((size_t)bh * TT + t) * HD;
    float qreg[HD];
#pragma unroll
    for (int d = 0; d < HD; d++) qreg[d] = qrow[d];

    float m = -1e30f, l = 0.f;
    float acc[HD];
#pragma unroll
    for (int d = 0; d < HD; d++) acc[d] = 0.f;

    const float wd = w_disc[h];
    const int nk = t0 + QB;                // keys in [0, nk)

    for (int s0 = 0; s0 < nk; s0 += KT) {
        __syncthreads();
        // Stage ka tile and v tile (64 rows x 64 floats each)
        const float* kbase = ka + ((size_t)bh * TT + s0) * HD;
#pragma unroll
        for (int it = 0; it < 8; it++) {
            int i = tid + it * 128;        // 0..1023 float4 slots
            int row = i >> 4;
            int c4 = i & 15;
            ((float4*)&skk[row][0])[c4] = ((const float4*)(kbase + row * HD))[c4];
            const float* vrow = qkv + (size_t)(b * TT + s0 + row) * (3 * CC) + 2 * CC + h * HD;
            ((float4*)&svv[row][0])[c4] = ((const float4*)vrow)[c4];
        }
        if (tid < KT) sb[tid] = wd * d_bias[h * TT + s0 + tid];
        __syncthreads();

        int jmax = t - s0 + 1;             // causal: keys s0+j <= t
        if (jmax > KT) jmax = KT;
        for (int j = 0; j < jmax; j++) {
            float s = 0.f;
#pragma unroll
            for (int d = 0; d < HD; d++) s += qreg[d] * skk[j][d];
            s = s * 0.125f + sb[j];

            if (s <= m) {
                float p = __expf(s - m);
                l += p;
#pragma unroll
                for (int d = 0; d < HD; d++) acc[d] += p * svv[j][d];
            } else {
                float corr = __expf(m - s);  // p = 1 at the new max
                l = l * corr + 1.f;
#pragma unroll
                for (int d = 0; d < HD; d++) acc[d] = acc[d] * corr + svv[j][d];
                m = s;
            }
        }
    }

    const float inv = 1.f / l;
    float* orow = ao + ((size_t)(b * TT + t) * HH + h) * HD;
#pragma unroll
    for (int d = 0; d < HD; d++) orow[d] = acc[d] * inv;
}

// ---------------------------------------------------------------------------
// Launch
// ---------------------------------------------------------------------------
extern "C" void kernel_launch(void* const* d_in, const int* in_sizes, int n_in,
                              void* d_out, int out_size)
{
    const float* x       = (const float*)d_in[0];
    const float* Wqkv    = (const float*)d_in[1];
    const float* Wproj   = (const float*)d_in[2];
    const float* W_recip = (const float*)d_in[3];
    const float* w_std   = (const float*)d_in[4];
    const float* w_rec   = (const float*)d_in[5];
    const float* w_disc  = (const float*)d_in[6];
    const float* d_bias  = (const float*)d_in[7];
    float* out = (float*)d_out;

    float *p_qkv, *p_qa, *p_ka, *p_ao;
    cudaGetSymbolAddress((void**)&p_qkv, g_qkv);
    cudaGetSymbolAddress((void**)&p_qa, g_qa);
    cudaGetSymbolAddress((void**)&p_ka, g_ka);
    cudaGetSymbolAddress((void**)&p_ao, g_ao);

    const int M = BB * TT;   // 4096

    // 1) qkv = x @ Wqkv^T   (4096 x 3072, K=1024)
    gemm_nt<<<dim3((3 * CC) / BN, M / BM), 256>>>(x, Wqkv, p_qkv, M, 3 * CC, CC);

    // 2) cross augmentation
    augment_kernel<<<BB * HH * TT, 64>>>(p_qkv, p_qa, p_ka, W_recip, w_std, w_rec);

    // 3) causal flash attention with key bias
    flash_kernel<<<dim3(TT / QB, BB * HH), 128>>>(p_qa, p_ka, p_qkv, d_bias, w_disc, p_ao);

    // 4) out = ao @ Wproj^T  (4096 x 1024, K=1024)
    gemm_nt<<<dim3(CC / BN, M / BM), 256>>>(p_ao, Wproj, out, M, CC, CC);
}

// round 3
// speedup vs baseline: 2.2984x; 2.2984x over previous
#include <cuda_runtime.h>
#include <math.h>

// Problem constants (fixed shapes)
#define BB 2
#define TT 2048
#define CC 1024
#define HH 16
#define HD 64
#define RR 8
#define DSTD 56

// Scratch (static device globals — no allocation)
__device__ float g_qkv[(size_t)BB * TT * 3 * CC];   // (B,T,3C)   48 MB
__device__ float g_qa[(size_t)BB * HH * TT * HD];   // (B,H,T,64) 16 MB
__device__ float g_ka[(size_t)BB * HH * TT * HD];   // (B,H,T,64) 16 MB
__device__ float g_ao[(size_t)BB * TT * CC];        // (B,T,C)    16 MB

// ---------------------------------------------------------------------------
// TF32 tensor-core GEMM (NT): C[m,n] = sum_k A[m,k] * B[n,k]
// A: (M,K) row-major, B: (N,K) row-major. M,N % 128 == 0, K % 32 == 0.
// 128x128x32 tile, 256 threads = 8 warps in 2(m) x 4(n); warp tile 64x32.
// mma.sync.aligned.m16n8k8 tf32, fp32 accumulate.
// ---------------------------------------------------------------------------
#define GBM 128
#define GBN 128
#define GBK 32
#define LDT 36   // padded row length (words); 36*4 bytes = 144, 16B aligned

__device__ __forceinline__ unsigned f2tf32(float f) {
    unsigned r;
    asm("cvt.rna.tf32.f32 %0, %1;" : "=r"(r) : "f"(f));
    return r;
}

__device__ __forceinline__ void mma_tf32(float& c0, float& c1, float& c2, float& c3,
                                         unsigned a0, unsigned a1, unsigned a2, unsigned a3,
                                         unsigned b0, unsigned b1) {
    asm volatile(
        "mma.sync.aligned.m16n8k8.row.col.f32.tf32.tf32.f32 "
        "{%0,%1,%2,%3}, {%4,%5,%6,%7}, {%8,%9}, {%0,%1,%2,%3};"
        : "+f"(c0), "+f"(c1), "+f"(c2), "+f"(c3)
        : "r"(a0), "r"(a1), "r"(a2), "r"(a3), "r"(b0), "r"(b1));
}

__global__ __launch_bounds__(256) void gemm_nt_tf32(
    const float* __restrict__ A, const float* __restrict__ B,
    float* __restrict__ C, int M, int N, int K)
{
    __shared__ unsigned As[GBM * LDT];   // [m][k], tf32 bits
    __shared__ unsigned Bs[GBN * LDT];   // [n][k], tf32 bits

    const int bm = blockIdx.y * GBM;
    const int bn = blockIdx.x * GBN;
    const int tid = threadIdx.x;
    const int wid = tid >> 5;
    const int lane = tid & 31;
    const int g = lane >> 2;      // group (0..7)
    const int q = lane & 3;       // quad  (0..3)
    const int wm = (wid >> 2) * 64;   // warp m offset (0 or 64)
    const int wn = (wid & 3) * 32;    // warp n offset (0..96)

    float acc[4][4][4];
#pragma unroll
    for (int i = 0; i < 4; i++)
#pragma unroll
        for (int j = 0; j < 4; j++)
#pragma unroll
            for (int r = 0; r < 4; r++) acc[i][j][r] = 0.f;

    for (int k0 = 0; k0 < K; k0 += GBK) {
        // Stage 128x32 A and B tiles: 1024 float4 each, 4 per thread each.
#pragma unroll
        for (int it = 0; it < 4; it++) {
            int f = tid + it * 256;       // 0..1023
            int row = f >> 3;             // 0..127
            int c4 = f & 7;               // 0..7
            float4 va = *(const float4*)(A + (size_t)(bm + row) * K + k0 + c4 * 4);
            unsigned* da = &As[row * LDT + c4 * 4];
            da[0] = f2tf32(va.x); da[1] = f2tf32(va.y);
            da[2] = f2tf32(va.z); da[3] = f2tf32(va.w);
            float4 vb = *(const float4*)(B + (size_t)(bn + row) * K + k0 + c4 * 4);
            unsigned* db = &Bs[row * LDT + c4 * 4];
            db[0] = f2tf32(vb.x); db[1] = f2tf32(vb.y);
            db[2] = f2tf32(vb.z); db[3] = f2tf32(vb.w);
        }
        __syncthreads();

#pragma unroll
        for (int kc = 0; kc < GBK / 8; kc++) {
            unsigned af[4][4];
#pragma unroll
            for (int mi = 0; mi < 4; mi++) {
                int m = wm + mi * 16 + g;
                const unsigned* p = &As[m * LDT + kc * 8 + q];
                af[mi][0] = p[0];
                af[mi][1] = p[8 * LDT];
                af[mi][2] = p[4];
                af[mi][3] = p[8 * LDT + 4];
            }
            unsigned bf[4][2];
#pragma unroll
            for (int ni = 0; ni < 4; ni++) {
                int n = wn + ni * 8 + g;
                const unsigned* p = &Bs[n * LDT + kc * 8 + q];
                bf[ni][0] = p[0];
                bf[ni][1] = p[4];
            }
#pragma unroll
            for (int mi = 0; mi < 4; mi++)
#pragma unroll
                for (int ni = 0; ni < 4; ni++)
                    mma_tf32(acc[mi][ni][0], acc[mi][ni][1], acc[mi][ni][2], acc[mi][ni][3],
                             af[mi][0], af[mi][1], af[mi][2], af[mi][3],
                             bf[ni][0], bf[ni][1]);
        }
        __syncthreads();
    }

    // Epilogue: c0,c1 at (g, q*2), c2,c3 at (g+8, q*2)
#pragma unroll
    for (int mi = 0; mi < 4; mi++) {
#pragma unroll
        for (int ni = 0; ni < 4; ni++) {
            int row = bm + wm + mi * 16 + g;
            int col = bn + wn + ni * 8 + q * 2;
            *(float2*)(C + (size_t)row * N + col) =
                make_float2(acc[mi][ni][0], acc[mi][ni][1]);
            *(float2*)(C + (size_t)(row + 8) * N + col) =
                make_float2(acc[mi][ni][2], acc[mi][ni][3]);
        }
    }
}

// ---------------------------------------------------------------------------
// Augmentation: for each (b,h,t) build
//   qa = [sqrt(w_std)*q[:56], sqrt(w_rec)*k_low]   (cross: q carries k_low)
//   ka = [sqrt(w_std)*k[:56], sqrt(w_rec)*q_low]
// ---------------------------------------------------------------------------
__global__ __launch_bounds__(64) void augment_kernel(
    const float* __restrict__ qkv, float* __restrict__ qa, float* __restrict__ ka,
    const float* __restrict__ W_recip, const float* __restrict__ w_std,
    const float* __restrict__ w_rec)
{
    const int idx = blockIdx.x;            // (b*H + h)*T + t
    const int t = idx % TT;
    const int h = (idx / TT) % HH;
    const int b = idx / (TT * HH);

    const float* base = qkv + (size_t)(b * TT + t) * (3 * CC);
    const int d = threadIdx.x;             // 0..63

    float qd = base[h * HD + d];
    float kd = base[CC + h * HD + d];

    __shared__ float sq[HD], sk[HD], qlow[RR], klow[RR];
    sq[d] = qd;
    sk[d] = kd;
    __syncthreads();

    if (d < RR) {
        float s = 0.f;
#pragma unroll
        for (int i = 0; i < HD; i++) s += sq[i] * W_recip[i * RR + d];
        qlow[d] = s;
    } else if (d < 2 * RR) {
        int r = d - RR;
        float s = 0.f;
#pragma unroll
        for (int i = 0; i < HD; i++) s += sk[i] * W_recip[i * RR + r];
        klow[r] = s;
    }
    __syncthreads();

    const float sws = sqrtf(w_std[h]);
    const float swr = sqrtf(w_rec[h]);
    float qav = (d < DSTD) ? sws * qd : swr * klow[d - DSTD];
    float kav = (d < DSTD) ? sws * kd : swr * qlow[d - DSTD];

    size_t o = ((size_t)idx) * HD + d;
    qa[o] = qav;
    ka[o] = kav;
}

// ---------------------------------------------------------------------------
// Flash attention (causal) with per-head key bias.
// Grid: (T/128, B*H). 128 threads, one query row per thread.
// ---------------------------------------------------------------------------
#define QB 128
#define KT 64

__global__ __launch_bounds__(128) void flash_kernel(
    const float* __restrict__ qa, const float* __restrict__ ka,
    const float* __restrict__ qkv, const float* __restrict__ d_bias,
    const float* __restrict__ w_disc, float* __restrict__ ao)
{
    const int bh = blockIdx.y;
    const int b = bh / HH;
    const int h = bh % HH;
    const int t0 = blockIdx.x * QB;
    const int tid = threadIdx.x;           // 0..127
    const int t = t0 + tid;                // this thread's query row

    __shared__ float skk[KT][HD];
    __shared__ float svv[KT][HD];
    __shared__ float sb[KT];

    const float* qrow = qa + ((size_t)bh * TT + t) * HD;
    float qreg[HD];
#pragma unroll
    for (int d = 0; d < HD; d++) qreg[d] = qrow[d];

    float m = -1e30f, l = 0.f;
    float acc[HD];
#pragma unroll
    for (int d = 0; d < HD; d++) acc[d] = 0.f;

    const float wd = w_disc[h];
    const int nk = t0 + QB;                // keys in [0, nk)

    for (int s0 = 0; s0 < nk; s0 += KT) {
        __syncthreads();
        const float* kbase = ka + ((size_t)bh * TT + s0) * HD;
#pragma unroll
        for (int it = 0; it < 8; it++) {
            int i = tid + it * 128;        // 0..1023 float4 slots
            int row = i >> 4;
            int c4 = i & 15;
            ((float4*)&skk[row][0])[c4] = ((const float4*)(kbase + row * HD))[c4];
            const float* vrow = qkv + (size_t)(b * TT + s0 + row) * (3 * CC) + 2 * CC + h * HD;
            ((float4*)&svv[row][0])[c4] = ((const float4*)vrow)[c4];
        }
        if (tid < KT) sb[tid] = wd * d_bias[h * TT + s0 + tid];
        __syncthreads();

        int jmax = t - s0 + 1;             // causal: keys s0+j <= t
        if (jmax > KT) jmax = KT;
        for (int j = 0; j < jmax; j++) {
            float s = 0.f;
#pragma unroll
            for (int d = 0; d < HD; d++) s += qreg[d] * skk[j][d];
            s = s * 0.125f + sb[j];

            if (s <= m) {
                float p = __expf(s - m);
                l += p;
#pragma unroll
                for (int d = 0; d < HD; d++) acc[d] += p * svv[j][d];
            } else {
                float corr = __expf(m - s);  // p = 1 at the new max
                l = l * corr + 1.f;
#pragma unroll
                for (int d = 0; d < HD; d++) acc[d] = acc[d] * corr + svv[j][d];
                m = s;
            }
        }
    }

    const float inv = 1.f / l;
    float* orow = ao + ((size_t)(b * TT + t) * HH + h) * HD;
#pragma unroll
    for (int d = 0; d < HD; d++) orow[d] = acc[d] * inv;
}

// ---------------------------------------------------------------------------
// Launch
// ---------------------------------------------------------------------------
extern "C" void kernel_launch(void* const* d_in, const int* in_sizes, int n_in,
                              void* d_out, int out_size)
{
    const float* x       = (const float*)d_in[0];
    const float* Wqkv    = (const float*)d_in[1];
    const float* Wproj   = (const float*)d_in[2];
    const float* W_recip = (const float*)d_in[3];
    const float* w_std   = (const float*)d_in[4];
    const float* w_rec   = (const float*)d_in[5];
    const float* w_disc  = (const float*)d_in[6];
    const float* d_bias  = (const float*)d_in[7];
    float* out = (float*)d_out;

    float *p_qkv, *p_qa, *p_ka, *p_ao;
    cudaGetSymbolAddress((void**)&p_qkv, g_qkv);
    cudaGetSymbolAddress((void**)&p_qa, g_qa);
    cudaGetSymbolAddress((void**)&p_ka, g_ka);
    cudaGetSymbolAddress((void**)&p_ao, g_ao);

    const int M = BB * TT;   // 4096

    // 1) qkv = x @ Wqkv^T   (4096 x 3072, K=1024)
    gemm_nt_tf32<<<dim3((3 * CC) / GBN, M / GBM), 256>>>(x, Wqkv, p_qkv, M, 3 * CC, CC);

    // 2) cross augmentation
    augment_kernel<<<BB * HH * TT, 64>>>(p_qkv, p_qa, p_ka, W_recip, w_std, w_rec);

    // 3) causal flash attention with key bias
    flash_kernel<<<dim3(TT / QB, BB * HH), 128>>>(p_qa, p_ka, p_qkv, d_bias, w_disc, p_ao);

    // 4) out = ao @ Wproj^T  (4096 x 1024, K=1024)
    gemm_nt_tf32<<<dim3(CC / GBN, M / GBM), 256>>>(p_ao, Wproj, out, M, CC, CC);
}

// round 4
// speedup vs baseline: 2.9545x; 1.2855x over previous
#include <cuda_runtime.h>
#include <math.h>

// Problem constants (fixed shapes)
#define BB 2
#define TT 2048
#define CC 1024
#define HH 16
#define HD 64
#define RR 8
#define DSTD 56

// Scratch (static device globals — no allocation)
__device__ float g_qkv[(size_t)BB * TT * 3 * CC];   // (B,T,3C)   48 MB
__device__ float g_qa[(size_t)BB * HH * TT * HD];   // (B,H,T,64) 16 MB
__device__ float g_ka[(size_t)BB * HH * TT * HD];   // (B,H,T,64) 16 MB
__device__ float g_ao[(size_t)BB * TT * CC];        // (B,T,C)    16 MB

__device__ __forceinline__ unsigned f2tf32(float f) {
    unsigned r;
    asm("cvt.rna.tf32.f32 %0, %1;" : "=r"(r) : "f"(f));
    return r;
}

__device__ __forceinline__ void mma_tf32(float& c0, float& c1, float& c2, float& c3,
                                         unsigned a0, unsigned a1, unsigned a2, unsigned a3,
                                         unsigned b0, unsigned b1) {
    asm volatile(
        "mma.sync.aligned.m16n8k8.row.col.f32.tf32.tf32.f32 "
        "{%0,%1,%2,%3}, {%4,%5,%6,%7}, {%8,%9}, {%0,%1,%2,%3};"
        : "+f"(c0), "+f"(c1), "+f"(c2), "+f"(c3)
        : "r"(a0), "r"(a1), "r"(a2), "r"(a3), "r"(b0), "r"(b1));
}

// ---------------------------------------------------------------------------
// TF32 tensor-core GEMM (NT): C[m,n] = sum_k A[m,k] * B[n,k]
// 128x128x32 tile, 256 threads = 8 warps (2m x 4n), warp tile 64x32.
// ---------------------------------------------------------------------------
#define GBM 128
#define GBN 128
#define GBK 32
#define LDT 36

__global__ __launch_bounds__(256) void gemm_nt_tf32(
    const float* __restrict__ A, const float* __restrict__ B,
    float* __restrict__ C, int M, int N, int K)
{
    __shared__ unsigned As[GBM * LDT];
    __shared__ unsigned Bs[GBN * LDT];

    const int bm = blockIdx.y * GBM;
    const int bn = blockIdx.x * GBN;
    const int tid = threadIdx.x;
    const int wid = tid >> 5;
    const int lane = tid & 31;
    const int g = lane >> 2;
    const int q = lane & 3;
    const int wm = (wid >> 2) * 64;
    const int wn = (wid & 3) * 32;

    float acc[4][4][4];
#pragma unroll
    for (int i = 0; i < 4; i++)
#pragma unroll
        for (int j = 0; j < 4; j++)
#pragma unroll
            for (int r = 0; r < 4; r++) acc[i][j][r] = 0.f;

    for (int k0 = 0; k0 < K; k0 += GBK) {
#pragma unroll
        for (int it = 0; it < 4; it++) {
            int f = tid + it * 256;
            int row = f >> 3;
            int c4 = f & 7;
            float4 va = *(const float4*)(A + (size_t)(bm + row) * K + k0 + c4 * 4);
            unsigned* da = &As[row * LDT + c4 * 4];
            da[0] = f2tf32(va.x); da[1] = f2tf32(va.y);
            da[2] = f2tf32(va.z); da[3] = f2tf32(va.w);
            float4 vb = *(const float4*)(B + (size_t)(bn + row) * K + k0 + c4 * 4);
            unsigned* db = &Bs[row * LDT + c4 * 4];
            db[0] = f2tf32(vb.x); db[1] = f2tf32(vb.y);
            db[2] = f2tf32(vb.z); db[3] = f2tf32(vb.w);
        }
        __syncthreads();

#pragma unroll
        for (int kc = 0; kc < GBK / 8; kc++) {
            unsigned af[4][4];
#pragma unroll
            for (int mi = 0; mi < 4; mi++) {
                int m = wm + mi * 16 + g;
                const unsigned* p = &As[m * LDT + kc * 8 + q];
                af[mi][0] = p[0];
                af[mi][1] = p[8 * LDT];
                af[mi][2] = p[4];
                af[mi][3] = p[8 * LDT + 4];
            }
            unsigned bf[4][2];
#pragma unroll
            for (int ni = 0; ni < 4; ni++) {
                int n = wn + ni * 8 + g;
                const unsigned* p = &Bs[n * LDT + kc * 8 + q];
                bf[ni][0] = p[0];
                bf[ni][1] = p[4];
            }
#pragma unroll
            for (int mi = 0; mi < 4; mi++)
#pragma unroll
                for (int ni = 0; ni < 4; ni++)
                    mma_tf32(acc[mi][ni][0], acc[mi][ni][1], acc[mi][ni][2], acc[mi][ni][3],
                             af[mi][0], af[mi][1], af[mi][2], af[mi][3],
                             bf[ni][0], bf[ni][1]);
        }
        __syncthreads();
    }

#pragma unroll
    for (int mi = 0; mi < 4; mi++) {
#pragma unroll
        for (int ni = 0; ni < 4; ni++) {
            int row = bm + wm + mi * 16 + g;
            int col = bn + wn + ni * 8 + q * 2;
            *(float2*)(C + (size_t)row * N + col) =
                make_float2(acc[mi][ni][0], acc[mi][ni][1]);
            *(float2*)(C + (size_t)(row + 8) * N + col) =
                make_float2(acc[mi][ni][2], acc[mi][ni][3]);
        }
    }
}

// ---------------------------------------------------------------------------
// Augmentation (unchanged)
// ---------------------------------------------------------------------------
__global__ __launch_bounds__(64) void augment_kernel(
    const float* __restrict__ qkv, float* __restrict__ qa, float* __restrict__ ka,
    const float* __restrict__ W_recip, const float* __restrict__ w_std,
    const float* __restrict__ w_rec)
{
    const int idx = blockIdx.x;
    const int t = idx % TT;
    const int h = (idx / TT) % HH;
    const int b = idx / (TT * HH);

    const float* base = qkv + (size_t)(b * TT + t) * (3 * CC);
    const int d = threadIdx.x;

    float qd = base[h * HD + d];
    float kd = base[CC + h * HD + d];

    __shared__ float sq[HD], sk[HD], qlow[RR], klow[RR];
    sq[d] = qd;
    sk[d] = kd;
    __syncthreads();

    if (d < RR) {
        float s = 0.f;
#pragma unroll
        for (int i = 0; i < HD; i++) s += sq[i] * W_recip[i * RR + d];
        qlow[d] = s;
    } else if (d < 2 * RR) {
        int r = d - RR;
        float s = 0.f;
#pragma unroll
        for (int i = 0; i < HD; i++) s += sk[i] * W_recip[i * RR + r];
        klow[r] = s;
    }
    __syncthreads();

    const float sws = sqrtf(w_std[h]);
    const float swr = sqrtf(w_rec[h]);
    float qav = (d < DSTD) ? sws * qd : swr * klow[d - DSTD];
    float kav = (d < DSTD) ? sws * kd : swr * qlow[d - DSTD];

    size_t o = ((size_t)idx) * HD + d;
    qa[o] = qav;
    ka[o] = kav;
}

// ---------------------------------------------------------------------------
// Tensor-core flash attention (causal) with per-head key bias.
// Grid: (T/128, B*H), 256 threads = 8 warps; warp handles 16 query rows.
// Key tiles of 64. QK^T and P*V via tf32 mma; online softmax in registers.
// smem: s_qp (Q staging, then per-warp P), s_k [key][dim], s_v [dim][key].
// ---------------------------------------------------------------------------
#define FP_QP (128 * 68)
#define FP_K  (64 * 68)
#define FP_V  (64 * 65)
#define FLASH_SMEM ((FP_QP + FP_K + FP_V) * 4 + 64 * 4)

__global__ __launch_bounds__(256) void flash_mma(
    const float* __restrict__ qa, const float* __restrict__ ka,
    const float* __restrict__ qkv, const float* __restrict__ d_bias,
    const float* __restrict__ w_disc, float* __restrict__ ao)
{
    extern __shared__ unsigned sm[];
    unsigned* s_qp = sm;                       // Q staging / P buffers
    unsigned* s_k  = sm + FP_QP;               // K tile [key][dim], pad 68
    unsigned* s_v  = sm + FP_QP + FP_K;        // V^T tile [dim][key], pad 65
    float*    s_b  = (float*)(sm + FP_QP + FP_K + FP_V);

    const int bh = blockIdx.y;
    const int b = bh >> 4;
    const int h = bh & 15;
    const int t0 = blockIdx.x * 128;
    const int tid = threadIdx.x;
    const int w = tid >> 5;
    const int lane = tid & 31;
    const int g = lane >> 2;
    const int q = lane & 3;

    // ---- Stage Q tile (128x64), scaled by 1/8, as tf32 ----
    const float* qbase = qa + ((size_t)bh * TT + t0) * HD;
#pragma unroll
    for (int it = 0; it < 8; it++) {
        int i = tid + it * 256;          // 0..2047 float4 slots
        int row = i >> 4, c4 = i & 15;
        float4 v = *(const float4*)(qbase + row * HD + c4 * 4);
        unsigned* d = &s_qp[row * 68 + c4 * 4];
        d[0] = f2tf32(v.x * 0.125f); d[1] = f2tf32(v.y * 0.125f);
        d[2] = f2tf32(v.z * 0.125f); d[3] = f2tf32(v.w * 0.125f);
    }
    __syncthreads();

    // Q fragments into registers (rows w*16+g, w*16+g+8)
    unsigned qf[8][4];
    {
        const int r0 = w * 16 + g;
#pragma unroll
        for (int kc = 0; kc < 8; kc++) {
            const unsigned* p = &s_qp[r0 * 68 + kc * 8 + q];
            qf[kc][0] = p[0];
            qf[kc][1] = p[8 * 68];
            qf[kc][2] = p[4];
            qf[kc][3] = p[8 * 68 + 4];
        }
    }
    __syncthreads();   // s_qp now reused as per-warp P buffers

    float m0 = -1e30f, m1 = -1e30f, l0 = 0.f, l1 = 0.f;
    float o[8][4];
#pragma unroll
    for (int nd = 0; nd < 8; nd++)
#pragma unroll
        for (int r = 0; r < 4; r++) o[nd][r] = 0.f;

    const float wd = w_disc[h];
    const int row0 = t0 + w * 16 + g;
    const int row1 = row0 + 8;

    for (int s0 = 0; s0 < t0 + 128; s0 += 64) {
        __syncthreads();
        // ---- Stage K [key][dim] and V^T [dim][key] as tf32 ----
        const float* kb = ka + ((size_t)bh * TT + s0) * HD;
        const float* vb = qkv + (size_t)(b * TT + s0) * (3 * CC) + 2 * CC + h * HD;
#pragma unroll
        for (int it = 0; it < 4; it++) {
            int i = tid + it * 256;      // 0..1023 float4 slots (64 rows x 16)
            int row = i >> 4, c4 = i & 15;
            float4 kv = *(const float4*)(kb + row * HD + c4 * 4);
            unsigned* dk = &s_k[row * 68 + c4 * 4];
            dk[0] = f2tf32(kv.x); dk[1] = f2tf32(kv.y);
            dk[2] = f2tf32(kv.z); dk[3] = f2tf32(kv.w);
            float4 vv = *(const float4*)(vb + (size_t)row * (3 * CC) + c4 * 4);
            s_v[(c4 * 4 + 0) * 65 + row] = f2tf32(vv.x);
            s_v[(c4 * 4 + 1) * 65 + row] = f2tf32(vv.y);
            s_v[(c4 * 4 + 2) * 65 + row] = f2tf32(vv.z);
            s_v[(c4 * 4 + 3) * 65 + row] = f2tf32(vv.w);
        }
        if (tid < 64) s_b[tid] = wd * d_bias[h * TT + s0 + tid];
        __syncthreads();

        // ---- QK^T: S[16 rows][64 keys] per warp ----
        float sa[8][4];
#pragma unroll
        for (int ni = 0; ni < 8; ni++)
#pragma unroll
            for (int r = 0; r < 4; r++) sa[ni][r] = 0.f;

#pragma unroll
        for (int kc = 0; kc < 8; kc++) {
            unsigned bfr[8][2];
#pragma unroll
            for (int ni = 0; ni < 8; ni++) {
                const unsigned* p = &s_k[(ni * 8 + g) * 68 + kc * 8 + q];
                bfr[ni][0] = p[0];
                bfr[ni][1] = p[4];
            }
#pragma unroll
            for (int ni = 0; ni < 8; ni++)
                mma_tf32(sa[ni][0], sa[ni][1], sa[ni][2], sa[ni][3],
                         qf[kc][0], qf[kc][1], qf[kc][2], qf[kc][3],
                         bfr[ni][0], bfr[ni][1]);
        }

        // ---- bias + causal mask + online softmax ----
        float mx0 = -1e30f, mx1 = -1e30f;
#pragma unroll
        for (int ni = 0; ni < 8; ni++) {
            int c = s0 + ni * 8 + 2 * q;
            float b0 = s_b[ni * 8 + 2 * q];
            float b1 = s_b[ni * 8 + 2 * q + 1];
            sa[ni][0] = (c     <= row0) ? sa[ni][0] + b0 : -1e30f;
            sa[ni][1] = (c + 1 <= row0) ? sa[ni][1] + b1 : -1e30f;
            sa[ni][2] = (c     <= row1) ? sa[ni][2] + b0 : -1e30f;
            sa[ni][3] = (c + 1 <= row1) ? sa[ni][3] + b1 : -1e30f;
            mx0 = fmaxf(mx0, fmaxf(sa[ni][0], sa[ni][1]));
            mx1 = fmaxf(mx1, fmaxf(sa[ni][2], sa[ni][3]));
        }
        mx0 = fmaxf(mx0, __shfl_xor_sync(0xffffffffu, mx0, 1));
        mx0 = fmaxf(mx0, __shfl_xor_sync(0xffffffffu, mx0, 2));
        mx1 = fmaxf(mx1, __shfl_xor_sync(0xffffffffu, mx1, 1));
        mx1 = fmaxf(mx1, __shfl_xor_sync(0xffffffffu, mx1, 2));

        float m0n = fmaxf(m0, mx0);
        float m1n = fmaxf(m1, mx1);
        float cr0 = __expf(m0 - m0n);
        float cr1 = __expf(m1 - m1n);

        unsigned* pr0 = &s_qp[(w * 16 + g) * 68];
        unsigned* pr1 = &s_qp[(w * 16 + g + 8) * 68];
        float rs0 = 0.f, rs1 = 0.f;
#pragma unroll
        for (int ni = 0; ni < 8; ni++) {
            float p00 = __expf(sa[ni][0] - m0n);
            float p01 = __expf(sa[ni][1] - m0n);
            float p10 = __expf(sa[ni][2] - m1n);
            float p11 = __expf(sa[ni][3] - m1n);
            rs0 += p00 + p01;
            rs1 += p10 + p11;
            int ci = ni * 8 + 2 * q;
            pr0[ci] = f2tf32(p00); pr0[ci + 1] = f2tf32(p01);
            pr1[ci] = f2tf32(p10); pr1[ci + 1] = f2tf32(p11);
        }
        rs0 += __shfl_xor_sync(0xffffffffu, rs0, 1);
        rs0 += __shfl_xor_sync(0xffffffffu, rs0, 2);
        rs1 += __shfl_xor_sync(0xffffffffu, rs1, 1);
        rs1 += __shfl_xor_sync(0xffffffffu, rs1, 2);

        l0 = l0 * cr0 + rs0;
        l1 = l1 * cr1 + rs1;
        m0 = m0n;
        m1 = m1n;
#pragma unroll
        for (int nd = 0; nd < 8; nd++) {
            o[nd][0] *= cr0; o[nd][1] *= cr0;
            o[nd][2] *= cr1; o[nd][3] *= cr1;
        }
        __syncwarp();   // P stores visible to warp before mma fragment loads

        // ---- P * V: O[16 rows][64 dims] ----
#pragma unroll
        for (int kc = 0; kc < 8; kc++) {
            unsigned a0 = pr0[kc * 8 + q];
            unsigned a1 = pr1[kc * 8 + q];
            unsigned a2 = pr0[kc * 8 + q + 4];
            unsigned a3 = pr1[kc * 8 + q + 4];
#pragma unroll
            for (int nd = 0; nd < 8; nd++) {
                const unsigned* p = &s_v[(nd * 8 + g) * 65 + kc * 8 + q];
                mma_tf32(o[nd][0], o[nd][1], o[nd][2], o[nd][3],
                         a0, a1, a2, a3, p[0], p[4]);
            }
        }
    }

    // ---- Epilogue: normalize and write (B,T,H,64) ----
    const float i0 = 1.f / l0;
    const float i1 = 1.f / l1;
    float* ob0 = ao + ((size_t)(b * TT + row0) * HH + h) * HD;
    float* ob1 = ao + ((size_t)(b * TT + row1) * HH + h) * HD;
#pragma unroll
    for (int nd = 0; nd < 8; nd++) {
        *(float2*)(ob0 + nd * 8 + 2 * q) = make_float2(o[nd][0] * i0, o[nd][1] * i0);
        *(float2*)(ob1 + nd * 8 + 2 * q) = make_float2(o[nd][2] * i1, o[nd][3] * i1);
    }
}

// ---------------------------------------------------------------------------
// Launch
// ---------------------------------------------------------------------------
extern "C" void kernel_launch(void* const* d_in, const int* in_sizes, int n_in,
                              void* d_out, int out_size)
{
    const float* x       = (const float*)d_in[0];
    const float* Wqkv    = (const float*)d_in[1];
    const float* Wproj   = (const float*)d_in[2];
    const float* W_recip = (const float*)d_in[3];
    const float* w_std   = (const float*)d_in[4];
    const float* w_rec   = (const float*)d_in[5];
    const float* w_disc  = (const float*)d_in[6];
    const float* d_bias  = (const float*)d_in[7];
    float* out = (float*)d_out;

    float *p_qkv, *p_qa, *p_ka, *p_ao;
    cudaGetSymbolAddress((void**)&p_qkv, g_qkv);
    cudaGetSymbolAddress((void**)&p_qa, g_qa);
    cudaGetSymbolAddress((void**)&p_ka, g_ka);
    cudaGetSymbolAddress((void**)&p_ao, g_ao);

    const int M = BB * TT;   // 4096

    cudaFuncSetAttribute(flash_mma, cudaFuncAttributeMaxDynamicSharedMemorySize,
                         FLASH_SMEM);

    // 1) qkv = x @ Wqkv^T
    gemm_nt_tf32<<<dim3((3 * CC) / GBN, M / GBM), 256>>>(x, Wqkv, p_qkv, M, 3 * CC, CC);

    // 2) cross augmentation
    augment_kernel<<<BB * HH * TT, 64>>>(p_qkv, p_qa, p_ka, W_recip, w_std, w_rec);

    // 3) tensor-core causal flash attention with key bias
    flash_mma<<<dim3(TT / 128, BB * HH), 256, FLASH_SMEM>>>(
        p_qa, p_ka, p_qkv, d_bias, w_disc, p_ao);

    // 4) out = ao @ Wproj^T
    gemm_nt_tf32<<<dim3(CC / GBN, M / GBM), 256>>>(p_ao, Wproj, out, M, CC, CC);
}

// round 5
// speedup vs baseline: 3.8383x; 1.2991x over previous
#include <cuda_runtime.h>
#include <cuda_fp16.h>
#include <math.h>

// Problem constants (fixed shapes)
#define BB 2
#define TT 2048
#define CC 1024
#define HH 16
#define HD 64
#define RR 8
#define DSTD 56

// Scratch (static device globals — no allocation)
__device__ float g_qkv[(size_t)BB * TT * 3 * CC];   // (B,T,3C)   48 MB
__device__ float g_qa[(size_t)BB * HH * TT * HD];   // (B,H,T,64) 16 MB
__device__ float g_ka[(size_t)BB * HH * TT * HD];   // (B,H,T,64) 16 MB
__device__ float g_ao[(size_t)BB * TT * CC];        // (B,T,C)    16 MB

__device__ __forceinline__ unsigned f2tf32(float f) {
    unsigned r;
    asm("cvt.rna.tf32.f32 %0, %1;" : "=r"(r) : "f"(f));
    return r;
}

__device__ __forceinline__ unsigned f22h2(float a, float b) {
    __half2 h = __floats2half2_rn(a, b);
    return *reinterpret_cast<unsigned*>(&h);
}

__device__ __forceinline__ void mma_tf32(float& c0, float& c1, float& c2, float& c3,
                                         unsigned a0, unsigned a1, unsigned a2, unsigned a3,
                                         unsigned b0, unsigned b1) {
    asm volatile(
        "mma.sync.aligned.m16n8k8.row.col.f32.tf32.tf32.f32 "
        "{%0,%1,%2,%3}, {%4,%5,%6,%7}, {%8,%9}, {%0,%1,%2,%3};"
        : "+f"(c0), "+f"(c1), "+f"(c2), "+f"(c3)
        : "r"(a0), "r"(a1), "r"(a2), "r"(a3), "r"(b0), "r"(b1));
}

__device__ __forceinline__ void mma_f16(float& c0, float& c1, float& c2, float& c3,
                                        unsigned a0, unsigned a1, unsigned a2, unsigned a3,
                                        unsigned b0, unsigned b1) {
    asm volatile(
        "mma.sync.aligned.m16n8k16.row.col.f32.f16.f16.f32 "
        "{%0,%1,%2,%3}, {%4,%5,%6,%7}, {%8,%9}, {%0,%1,%2,%3};"
        : "+f"(c0), "+f"(c1), "+f"(c2), "+f"(c3)
        : "r"(a0), "r"(a1), "r"(a2), "r"(a3), "r"(b0), "r"(b1));
}

// ---------------------------------------------------------------------------
// TF32 tensor-core GEMM (NT): C[m,n] = sum_k A[m,k] * B[n,k]
// 128x128x32 tile, 256 threads = 8 warps (2m x 4n), warp tile 64x32.
// ---------------------------------------------------------------------------
#define GBM 128
#define GBN 128
#define GBK 32
#define LDT 36

__global__ __launch_bounds__(256) void gemm_nt_tf32(
    const float* __restrict__ A, const float* __restrict__ B,
    float* __restrict__ C, int M, int N, int K)
{
    __shared__ unsigned As[GBM * LDT];
    __shared__ unsigned Bs[GBN * LDT];

    const int bm = blockIdx.y * GBM;
    const int bn = blockIdx.x * GBN;
    const int tid = threadIdx.x;
    const int wid = tid >> 5;
    const int lane = tid & 31;
    const int g = lane >> 2;
    const int q = lane & 3;
    const int wm = (wid >> 2) * 64;
    const int wn = (wid & 3) * 32;

    float acc[4][4][4];
#pragma unroll
    for (int i = 0; i < 4; i++)
#pragma unroll
        for (int j = 0; j < 4; j++)
#pragma unroll
            for (int r = 0; r < 4; r++) acc[i][j][r] = 0.f;

    for (int k0 = 0; k0 < K; k0 += GBK) {
#pragma unroll
        for (int it = 0; it < 4; it++) {
            int f = tid + it * 256;
            int row = f >> 3;
            int c4 = f & 7;
            float4 va = *(const float4*)(A + (size_t)(bm + row) * K + k0 + c4 * 4);
            unsigned* da = &As[row * LDT + c4 * 4];
            da[0] = f2tf32(va.x); da[1] = f2tf32(va.y);
            da[2] = f2tf32(va.z); da[3] = f2tf32(va.w);
            float4 vb = *(const float4*)(B + (size_t)(bn + row) * K + k0 + c4 * 4);
            unsigned* db = &Bs[row * LDT + c4 * 4];
            db[0] = f2tf32(vb.x); db[1] = f2tf32(vb.y);
            db[2] = f2tf32(vb.z); db[3] = f2tf32(vb.w);
        }
        __syncthreads();

#pragma unroll
        for (int kc = 0; kc < GBK / 8; kc++) {
            unsigned af[4][4];
#pragma unroll
            for (int mi = 0; mi < 4; mi++) {
                int m = wm + mi * 16 + g;
                const unsigned* p = &As[m * LDT + kc * 8 + q];
                af[mi][0] = p[0];
                af[mi][1] = p[8 * LDT];
                af[mi][2] = p[4];
                af[mi][3] = p[8 * LDT + 4];
            }
            unsigned bf[4][2];
#pragma unroll
            for (int ni = 0; ni < 4; ni++) {
                int n = wn + ni * 8 + g;
                const unsigned* p = &Bs[n * LDT + kc * 8 + q];
                bf[ni][0] = p[0];
                bf[ni][1] = p[4];
            }
#pragma unroll
            for (int mi = 0; mi < 4; mi++)
#pragma unroll
                for (int ni = 0; ni < 4; ni++)
                    mma_tf32(acc[mi][ni][0], acc[mi][ni][1], acc[mi][ni][2], acc[mi][ni][3],
                             af[mi][0], af[mi][1], af[mi][2], af[mi][3],
                             bf[ni][0], bf[ni][1]);
        }
        __syncthreads();
    }

#pragma unroll
    for (int mi = 0; mi < 4; mi++) {
#pragma unroll
        for (int ni = 0; ni < 4; ni++) {
            int row = bm + wm + mi * 16 + g;
            int col = bn + wn + ni * 8 + q * 2;
            *(float2*)(C + (size_t)row * N + col) =
                make_float2(acc[mi][ni][0], acc[mi][ni][1]);
            *(float2*)(C + (size_t)(row + 8) * N + col) =
                make_float2(acc[mi][ni][2], acc[mi][ni][3]);
        }
    }
}

// ---------------------------------------------------------------------------
// Augmentation: 4 (b,h,t) rows per 256-thread block.
// ---------------------------------------------------------------------------
__global__ __launch_bounds__(256) void augment_kernel(
    const float* __restrict__ qkv, float* __restrict__ qa, float* __restrict__ ka,
    const float* __restrict__ W_recip, const float* __restrict__ w_std,
    const float* __restrict__ w_rec)
{
    const int grp = threadIdx.x >> 6;      // 0..3
    const int d = threadIdx.x & 63;
    const int idx = blockIdx.x * 4 + grp;  // (b*H + h)*T + t
    const int t = idx % TT;
    const int h = (idx / TT) % HH;
    const int b = idx / (TT * HH);

    const float* base = qkv + (size_t)(b * TT + t) * (3 * CC);

    float qd = base[h * HD + d];
    float kd = base[CC + h * HD + d];

    __shared__ float sq[4][HD], sk[4][HD], qlow[4][RR], klow[4][RR];
    sq[grp][d] = qd;
    sk[grp][d] = kd;
    __syncthreads();

    if (d < RR) {
        float s = 0.f;
#pragma unroll
        for (int i = 0; i < HD; i++) s += sq[grp][i] * W_recip[i * RR + d];
        qlow[grp][d] = s;
    } else if (d < 2 * RR) {
        int r = d - RR;
        float s = 0.f;
#pragma unroll
        for (int i = 0; i < HD; i++) s += sk[grp][i] * W_recip[i * RR + r];
        klow[grp][r] = s;
    }
    __syncthreads();

    const float sws = sqrtf(w_std[h]);
    const float swr = sqrtf(w_rec[h]);
    float qav = (d < DSTD) ? sws * qd : swr * klow[grp][d - DSTD];
    float kav = (d < DSTD) ? sws * kd : swr * qlow[grp][d - DSTD];

    size_t o = ((size_t)idx) * HD + d;
    qa[o] = qav;
    ka[o] = kav;
}

// ---------------------------------------------------------------------------
// Tensor-core flash attention (causal) with per-head key bias.
// Grid: (T/128, B*H), 256 threads = 8 warps; warp handles 16 query rows.
// QK^T: tf32 mma, K tile [key][dim] pad 68.
// P*V:  fp16 m16n8k16, P kept in registers (C-layout == A-layout),
//       V staged as half [dim][key] pad 72 (conflict-free half2 loads).
// Q staging region (128x68 words) is overlaid with K+V+bias.
// ---------------------------------------------------------------------------
#define SM_WORDS (128 * 68)          // 8704 words = 34816 B
#define SV_OFF   (64 * 68)           // K tile: 4352 words
#define SB_OFF   (SV_OFF + 64 * 72 / 2)   // V half tile: 2304 words

__global__ __launch_bounds__(256) void flash_mma(
    const float* __restrict__ qa, const float* __restrict__ ka,
    const float* __restrict__ qkv, const float* __restrict__ d_bias,
    const float* __restrict__ w_disc, float* __restrict__ ao)
{
    __shared__ unsigned sm[SM_WORDS];
    unsigned* s_k = sm;                        // [key][dim] tf32, pad 68
    __half*   s_v = (__half*)(sm + SV_OFF);    // [dim][key] half, pad 72
    float*    s_b = (float*)(sm + SB_OFF);     // bias [64]

    const int bh = blockIdx.y;
    const int b = bh >> 4;
    const int h = bh & 15;
    const int t0 = blockIdx.x * 128;
    const int tid = threadIdx.x;
    const int w = tid >> 5;
    const int lane = tid & 31;
    const int g = lane >> 2;
    const int q = lane & 3;

    // ---- Stage Q tile (128x64), scaled by 1/8, as tf32 (uses whole sm) ----
    const float* qbase = qa + ((size_t)bh * TT + t0) * HD;
#pragma unroll
    for (int it = 0; it < 8; it++) {
        int i = tid + it * 256;
        int row = i >> 4, c4 = i & 15;
        float4 v = *(const float4*)(qbase + row * HD + c4 * 4);
        unsigned* d = &sm[row * 68 + c4 * 4];
        d[0] = f2tf32(v.x * 0.125f); d[1] = f2tf32(v.y * 0.125f);
        d[2] = f2tf32(v.z * 0.125f); d[3] = f2tf32(v.w * 0.125f);
    }
    __syncthreads();

    // Q fragments into registers (rows w*16+g, w*16+g+8)
    unsigned qf[8][4];
    {
        const int r0 = w * 16 + g;
#pragma unroll
        for (int kc = 0; kc < 8; kc++) {
            const unsigned* p = &sm[r0 * 68 + kc * 8 + q];
            qf[kc][0] = p[0];
            qf[kc][1] = p[8 * 68];
            qf[kc][2] = p[4];
            qf[kc][3] = p[8 * 68 + 4];
        }
    }

    float m0 = -1e30f, m1 = -1e30f, l0 = 0.f, l1 = 0.f;
    float o[8][4];
#pragma unroll
    for (int nd = 0; nd < 8; nd++)
#pragma unroll
        for (int r = 0; r < 4; r++) o[nd][r] = 0.f;

    const float wd = w_disc[h];
    const int row0 = t0 + w * 16 + g;
    const int row1 = row0 + 8;

    for (int s0 = 0; s0 < t0 + 128; s0 += 64) {
        __syncthreads();   // previous tile's smem reads done (also covers Q-frag reads)
        // ---- Stage K [key][dim] tf32 and V [dim][key] half ----
        const float* kb = ka + ((size_t)bh * TT + s0) * HD;
        const float* vb = qkv + (size_t)(b * TT + s0) * (3 * CC) + 2 * CC + h * HD;
#pragma unroll
        for (int it = 0; it < 4; it++) {
            int i = tid + it * 256;      // 64 rows x 16 float4
            int row = i >> 4, c4 = i & 15;
            float4 kv = *(const float4*)(kb + row * HD + c4 * 4);
            unsigned* dk = &s_k[row * 68 + c4 * 4];
            dk[0] = f2tf32(kv.x); dk[1] = f2tf32(kv.y);
            dk[2] = f2tf32(kv.z); dk[3] = f2tf32(kv.w);
            float4 vv = *(const float4*)(vb + (size_t)row * (3 * CC) + c4 * 4);
            s_v[(c4 * 4 + 0) * 72 + row] = __float2half(vv.x);
            s_v[(c4 * 4 + 1) * 72 + row] = __float2half(vv.y);
            s_v[(c4 * 4 + 2) * 72 + row] = __float2half(vv.z);
            s_v[(c4 * 4 + 3) * 72 + row] = __float2half(vv.w);
        }
        if (tid < 64) s_b[tid] = wd * d_bias[h * TT + s0 + tid];
        __syncthreads();

        // ---- QK^T (tf32): S[16 rows][64 keys] per warp ----
        float sa[8][4];
#pragma unroll
        for (int ni = 0; ni < 8; ni++)
#pragma unroll
            for (int r = 0; r < 4; r++) sa[ni][r] = 0.f;

#pragma unroll
        for (int kc = 0; kc < 8; kc++) {
            unsigned bfr[8][2];
#pragma unroll
            for (int ni = 0; ni < 8; ni++) {
                const unsigned* p = &s_k[(ni * 8 + g) * 68 + kc * 8 + q];
                bfr[ni][0] = p[0];
                bfr[ni][1] = p[4];
            }
#pragma unroll
            for (int ni = 0; ni < 8; ni++)
                mma_tf32(sa[ni][0], sa[ni][1], sa[ni][2], sa[ni][3],
                         qf[kc][0], qf[kc][1], qf[kc][2], qf[kc][3],
                         bfr[ni][0], bfr[ni][1]);
        }

        // ---- bias + causal mask + online softmax ----
        float mx0 = -1e30f, mx1 = -1e30f;
#pragma unroll
        for (int ni = 0; ni < 8; ni++) {
            int c = s0 + ni * 8 + 2 * q;
            float b0 = s_b[ni * 8 + 2 * q];
            float b1 = s_b[ni * 8 + 2 * q + 1];
            sa[ni][0] = (c     <= row0) ? sa[ni][0] + b0 : -1e30f;
            sa[ni][1] = (c + 1 <= row0) ? sa[ni][1] + b1 : -1e30f;
            sa[ni][2] = (c     <= row1) ? sa[ni][2] + b0 : -1e30f;
            sa[ni][3] = (c + 1 <= row1) ? sa[ni][3] + b1 : -1e30f;
            mx0 = fmaxf(mx0, fmaxf(sa[ni][0], sa[ni][1]));
            mx1 = fmaxf(mx1, fmaxf(sa[ni][2], sa[ni][3]));
        }
        mx0 = fmaxf(mx0, __shfl_xor_sync(0xffffffffu, mx0, 1));
        mx0 = fmaxf(mx0, __shfl_xor_sync(0xffffffffu, mx0, 2));
        mx1 = fmaxf(mx1, __shfl_xor_sync(0xffffffffu, mx1, 1));
        mx1 = fmaxf(mx1, __shfl_xor_sync(0xffffffffu, mx1, 2));

        float m0n = fmaxf(m0, mx0);
        float m1n = fmaxf(m1, mx1);
        float cr0 = __expf(m0 - m0n);
        float cr1 = __expf(m1 - m1n);

        // P in registers, converted straight to fp16 A-fragments
        unsigned ph0[8], ph1[8];
        float rs0 = 0.f, rs1 = 0.f;
#pragma unroll
        for (int ni = 0; ni < 8; ni++) {
            float p00 = __expf(sa[ni][0] - m0n);
            float p01 = __expf(sa[ni][1] - m0n);
            float p10 = __expf(sa[ni][2] - m1n);
            float p11 = __expf(sa[ni][3] - m1n);
            rs0 += p00 + p01;
            rs1 += p10 + p11;
            ph0[ni] = f22h2(p00, p01);
            ph1[ni] = f22h2(p10, p11);
        }
        rs0 += __shfl_xor_sync(0xffffffffu, rs0, 1);
        rs0 += __shfl_xor_sync(0xffffffffu, rs0, 2);
        rs1 += __shfl_xor_sync(0xffffffffu, rs1, 1);
        rs1 += __shfl_xor_sync(0xffffffffu, rs1, 2);

        l0 = l0 * cr0 + rs0;
        l1 = l1 * cr1 + rs1;
        m0 = m0n;
        m1 = m1n;
#pragma unroll
        for (int nd = 0; nd < 8; nd++) {
            o[nd][0] *= cr0; o[nd][1] *= cr0;
            o[nd][2] *= cr1; o[nd][3] *= cr1;
        }

        // ---- P * V (fp16 m16n8k16): O[16 rows][64 dims] ----
#pragma unroll
        for (int kc = 0; kc < 4; kc++) {
            unsigned a0 = ph0[2 * kc];
            unsigned a1 = ph1[2 * kc];
            unsigned a2 = ph0[2 * kc + 1];
            unsigned a3 = ph1[2 * kc + 1];
#pragma unroll
            for (int nd = 0; nd < 8; nd++) {
                const __half* vp = &s_v[(nd * 8 + g) * 72 + kc * 16 + 2 * q];
                unsigned b0 = *(const unsigned*)(vp);
                unsigned b1 = *(const unsigned*)(vp + 8);
                mma_f16(o[nd][0], o[nd][1], o[nd][2], o[nd][3],
                        a0, a1, a2, a3, b0, b1);
            }
        }
    }

    // ---- Epilogue: normalize and write (B,T,H,64) ----
    const float i0 = 1.f / l0;
    const float i1 = 1.f / l1;
    float* ob0 = ao + ((size_t)(b * TT + row0) * HH + h) * HD;
    float* ob1 = ao + ((size_t)(b * TT + row1) * HH + h) * HD;
#pragma unroll
    for (int nd = 0; nd < 8; nd++) {
        *(float2*)(ob0 + nd * 8 + 2 * q) = make_float2(o[nd][0] * i0, o[nd][1] * i0);
        *(float2*)(ob1 + nd * 8 + 2 * q) = make_float2(o[nd][2] * i1, o[nd][3] * i1);
    }
}

// ---------------------------------------------------------------------------
// Launch
// ---------------------------------------------------------------------------
extern "C" void kernel_launch(void* const* d_in, const int* in_sizes, int n_in,
                              void* d_out, int out_size)
{
    const float* x       = (const float*)d_in[0];
    const float* Wqkv    = (const float*)d_in[1];
    const float* Wproj   = (const float*)d_in[2];
    const float* W_recip = (const float*)d_in[3];
    const float* w_std   = (const float*)d_in[4];
    const float* w_rec   = (const float*)d_in[5];
    const float* w_disc  = (const float*)d_in[6];
    const float* d_bias  = (const float*)d_in[7];
    float* out = (float*)d_out;

    float *p_qkv, *p_qa, *p_ka, *p_ao;
    cudaGetSymbolAddress((void**)&p_qkv, g_qkv);
    cudaGetSymbolAddress((void**)&p_qa, g_qa);
    cudaGetSymbolAddress((void**)&p_ka, g_ka);
    cudaGetSymbolAddress((void**)&p_ao, g_ao);

    const int M = BB * TT;   // 4096

    // 1) qkv = x @ Wqkv^T
    gemm_nt_tf32<<<dim3((3 * CC) / GBN, M / GBM), 256>>>(x, Wqkv, p_qkv, M, 3 * CC, CC);

    // 2) cross augmentation
    augment_kernel<<<BB * HH * TT / 4, 256>>>(p_qkv, p_qa, p_ka, W_recip, w_std, w_rec);

    // 3) tensor-core causal flash attention with key bias
    flash_mma<<<dim3(TT / 128, BB * HH), 256>>>(
        p_qa, p_ka, p_qkv, d_bias, w_disc, p_ao);

    // 4) out = ao @ Wproj^T
    gemm_nt_tf32<<<dim3(CC / GBN, M / GBM), 256>>>(p_ao, Wproj, out, M, CC, CC);
}

// round 6
// speedup vs baseline: 6.8045x; 1.7728x over previous
#include <cuda_runtime.h>
#include <cuda_fp16.h>
#include <math.h>

// Problem constants (fixed shapes)
#define BB 2
#define TT 2048
#define CC 1024
#define HH 16
#define HD 64
#define RR 8
#define DSTD 56

// Scratch (static device globals — no allocation)
__device__ float g_qkv[(size_t)BB * TT * 3 * CC];   // (B,T,3C)   48 MB
__device__ float g_qa[(size_t)BB * HH * TT * HD];   // (B,H,T,64) 16 MB
__device__ float g_ka[(size_t)BB * HH * TT * HD];   // (B,H,T,64) 16 MB
__device__ float g_ao[(size_t)BB * TT * CC];        // (B,T,C)    16 MB

__device__ __forceinline__ unsigned f22h2(float a, float b) {
    __half2 h = __floats2half2_rn(a, b);
    return *reinterpret_cast<unsigned*>(&h);
}

__device__ __forceinline__ void mma_f16(float& c0, float& c1, float& c2, float& c3,
                                        unsigned a0, unsigned a1, unsigned a2, unsigned a3,
                                        unsigned b0, unsigned b1) {
    asm volatile(
        "mma.sync.aligned.m16n8k16.row.col.f32.f16.f16.f32 "
        "{%0,%1,%2,%3}, {%4,%5,%6,%7}, {%8,%9}, {%0,%1,%2,%3};"
        : "+f"(c0), "+f"(c1), "+f"(c2), "+f"(c3)
        : "r"(a0), "r"(a1), "r"(a2), "r"(a3), "r"(b0), "r"(b1));
}

// ---------------------------------------------------------------------------
// FP16 tensor-core GEMM (NT), double-buffered: C[m,n] = sum_k A[m,k]*B[n,k]
// 128x128x32 tile, 256 threads = 8 warps (2m x 4n), warp tile 64x32.
// smem: half [row][40] (pad 8 halves -> conflict-free half2 fragment loads).
// ---------------------------------------------------------------------------
#define HBM 128
#define HBN 128
#define HBK 32
#define LDH 40

__global__ __launch_bounds__(256) void gemm_nt_f16(
    const float* __restrict__ A, const float* __restrict__ B,
    float* __restrict__ C, int M, int N, int K)
{
    __shared__ __align__(16) __half sA[2][HBM * LDH];
    __shared__ __align__(16) __half sB[2][HBN * LDH];

    const int bm = blockIdx.y * HBM;
    const int bn = blockIdx.x * HBN;
    const int tid = threadIdx.x;
    const int wid = tid >> 5;
    const int lane = tid & 31;
    const int g = lane >> 2;
    const int q = lane & 3;
    const int wm = (wid >> 2) * 64;
    const int wn = (wid & 3) * 32;

    float acc[4][4][4];
#pragma unroll
    for (int i = 0; i < 4; i++)
#pragma unroll
        for (int j = 0; j < 4; j++)
#pragma unroll
            for (int r = 0; r < 4; r++) acc[i][j][r] = 0.f;

    float4 ra[4], rb[4];
    const int nk = K / HBK;

    // Prologue: load tile 0
#pragma unroll
    for (int it = 0; it < 4; it++) {
        int f = tid + it * 256;
        int row = f >> 3, c4 = f & 7;
        ra[it] = *(const float4*)(A + (size_t)(bm + row) * K + c4 * 4);
        rb[it] = *(const float4*)(B + (size_t)(bn + row) * K + c4 * 4);
    }
#pragma unroll
    for (int it = 0; it < 4; it++) {
        int f = tid + it * 256;
        int row = f >> 3, c4 = f & 7;
        *(uint2*)&sA[0][row * LDH + c4 * 4] =
            make_uint2(f22h2(ra[it].x, ra[it].y), f22h2(ra[it].z, ra[it].w));
        *(uint2*)&sB[0][row * LDH + c4 * 4] =
            make_uint2(f22h2(rb[it].x, rb[it].y), f22h2(rb[it].z, rb[it].w));
    }
    __syncthreads();

    for (int k0 = 0; k0 < nk; k0++) {
        const int cur = k0 & 1;
        if (k0 + 1 < nk) {
            const int koff = (k0 + 1) * HBK;
#pragma unroll
            for (int it = 0; it < 4; it++) {
                int f = tid + it * 256;
                int row = f >> 3, c4 = f & 7;
                ra[it] = *(const float4*)(A + (size_t)(bm + row) * K + koff + c4 * 4);
                rb[it] = *(const float4*)(B + (size_t)(bn + row) * K + koff + c4 * 4);
            }
        }

#pragma unroll
        for (int kc = 0; kc < 2; kc++) {
            unsigned af[4][4];
#pragma unroll
            for (int mi = 0; mi < 4; mi++) {
                const __half* p = &sA[cur][(wm + mi * 16 + g) * LDH + kc * 16 + 2 * q];
                af[mi][0] = *(const unsigned*)(p);
                af[mi][1] = *(const unsigned*)(p + 8 * LDH);
                af[mi][2] = *(const unsigned*)(p + 8);
                af[mi][3] = *(const unsigned*)(p + 8 * LDH + 8);
            }
            unsigned bf[4][2];
#pragma unroll
            for (int ni = 0; ni < 4; ni++) {
                const __half* p = &sB[cur][(wn + ni * 8 + g) * LDH + kc * 16 + 2 * q];
                bf[ni][0] = *(const unsigned*)(p);
                bf[ni][1] = *(const unsigned*)(p + 8);
            }
#pragma unroll
            for (int mi = 0; mi < 4; mi++)
#pragma unroll
                for (int ni = 0; ni < 4; ni++)
                    mma_f16(acc[mi][ni][0], acc[mi][ni][1], acc[mi][ni][2], acc[mi][ni][3],
                            af[mi][0], af[mi][1], af[mi][2], af[mi][3],
                            bf[ni][0], bf[ni][1]);
        }

        if (k0 + 1 < nk) {
            const int nxt = cur ^ 1;
#pragma unroll
            for (int it = 0; it < 4; it++) {
                int f = tid + it * 256;
                int row = f >> 3, c4 = f & 7;
                *(uint2*)&sA[nxt][row * LDH + c4 * 4] =
                    make_uint2(f22h2(ra[it].x, ra[it].y), f22h2(ra[it].z, ra[it].w));
                *(uint2*)&sB[nxt][row * LDH + c4 * 4] =
                    make_uint2(f22h2(rb[it].x, rb[it].y), f22h2(rb[it].z, rb[it].w));
            }
            __syncthreads();
        }
    }

#pragma unroll
    for (int mi = 0; mi < 4; mi++) {
#pragma unroll
        for (int ni = 0; ni < 4; ni++) {
            int row = bm + wm + mi * 16 + g;
            int col = bn + wn + ni * 8 + q * 2;
            *(float2*)(C + (size_t)row * N + col) =
                make_float2(acc[mi][ni][0], acc[mi][ni][1]);
            *(float2*)(C + (size_t)(row + 8) * N + col) =
                make_float2(acc[mi][ni][2], acc[mi][ni][3]);
        }
    }
}

// ---------------------------------------------------------------------------
// Augmentation: 4 (b,h,t) rows per 256-thread block.
// ---------------------------------------------------------------------------
__global__ __launch_bounds__(256) void augment_kernel(
    const float* __restrict__ qkv, float* __restrict__ qa, float* __restrict__ ka,
    const float* __restrict__ W_recip, const float* __restrict__ w_std,
    const float* __restrict__ w_rec)
{
    const int grp = threadIdx.x >> 6;
    const int d = threadIdx.x & 63;
    const int idx = blockIdx.x * 4 + grp;
    const int t = idx % TT;
    const int h = (idx / TT) % HH;
    const int b = idx / (TT * HH);

    const float* base = qkv + (size_t)(b * TT + t) * (3 * CC);

    float qd = base[h * HD + d];
    float kd = base[CC + h * HD + d];

    __shared__ float sq[4][HD], sk[4][HD], qlow[4][RR], klow[4][RR];
    sq[grp][d] = qd;
    sk[grp][d] = kd;
    __syncthreads();

    if (d < RR) {
        float s = 0.f;
#pragma unroll
        for (int i = 0; i < HD; i++) s += sq[grp][i] * W_recip[i * RR + d];
        qlow[grp][d] = s;
    } else if (d < 2 * RR) {
        int r = d - RR;
        float s = 0.f;
#pragma unroll
        for (int i = 0; i < HD; i++) s += sk[grp][i] * W_recip[i * RR + r];
        klow[grp][r] = s;
    }
    __syncthreads();

    const float sws = sqrtf(w_std[h]);
    const float swr = sqrtf(w_rec[h]);
    float qav = (d < DSTD) ? sws * qd : swr * klow[grp][d - DSTD];
    float kav = (d < DSTD) ? sws * kd : swr * qlow[grp][d - DSTD];

    size_t o = ((size_t)idx) * HD + d;
    qa[o] = qav;
    ka[o] = kav;
}

// ---------------------------------------------------------------------------
// FP16 tensor-core flash attention (causal) with per-head key bias.
// Grid: (T/128, B*H), 256 threads = 8 warps; warp handles 16 query rows.
// QK^T and P*V via fp16 m16n8k16 (fp32 accum, fp32 softmax).
// K half [key][72], V half [dim][key] pad 72, Q staged half [row][72]
// overlaid on the K/V region (Q frags live in registers).
// ---------------------------------------------------------------------------
#define LDQ 72
#define FK_BYTES (64 * LDQ * 2)          // 9216
#define FSM_BYTES (2 * FK_BYTES + 256)   // K + V + bias

__global__ __launch_bounds__(256) void flash_mma(
    const float* __restrict__ qa, const float* __restrict__ ka,
    const float* __restrict__ qkv, const float* __restrict__ d_bias,
    const float* __restrict__ w_disc, float* __restrict__ ao)
{
    __shared__ __align__(16) unsigned char smbuf[FSM_BYTES];
    __half* s_q = (__half*)smbuf;                    // staging only (128x72 > region, see below)
    __half* s_k = (__half*)smbuf;                    // [key][72]
    __half* s_v = (__half*)(smbuf + FK_BYTES);       // [dim][key] pad 72
    float*  s_b = (float*)(smbuf + 2 * FK_BYTES);    // bias [64]

    const int bh = blockIdx.y;
    const int b = bh >> 4;
    const int h = bh & 15;
    const int t0 = blockIdx.x * 128;
    const int tid = threadIdx.x;
    const int w = tid >> 5;
    const int lane = tid & 31;
    const int g = lane >> 2;
    const int q = lane & 3;

    // ---- Stage Q (two half-tiles of 64 rows to fit the smem region),
    //      scaled by 1/8, as half; pull fragments to registers.
    unsigned qf[4][4];
    const int r0 = w * 16 + g;
    const float* qbase = qa + ((size_t)bh * TT + t0) * HD;
#pragma unroll
    for (int half_t = 0; half_t < 2; half_t++) {
        // stage rows [half_t*64, half_t*64+64)
#pragma unroll
        for (int it = 0; it < 4; it++) {
            int i = tid + it * 256;          // 0..1023 float4 slots (64 rows x 16)
            int row = i >> 4, c4 = i & 15;
            float4 v = *(const float4*)(qbase + (size_t)(half_t * 64 + row) * HD + c4 * 4);
            *(uint2*)&s_q[row * LDQ + c4 * 4] =
                make_uint2(f22h2(v.x * 0.125f, v.y * 0.125f),
                           f22h2(v.z * 0.125f, v.w * 0.125f));
        }
        __syncthreads();
        if ((r0 >> 6) == half_t) {           // this warp's rows are in this half
            int rr = r0 & 63;
#pragma unroll
            for (int kc = 0; kc < 4; kc++) {
                const __half* p = &s_q[rr * LDQ + kc * 16 + 2 * q];
                qf[kc][0] = *(const unsigned*)(p);
                qf[kc][1] = *(const unsigned*)(p + 8 * LDQ);
                qf[kc][2] = *(const unsigned*)(p + 8);
                qf[kc][3] = *(const unsigned*)(p + 8 * LDQ + 8);
            }
        }
        __syncthreads();
    }

    float m0 = -1e30f, m1 = -1e30f, l0 = 0.f, l1 = 0.f;
    float o[8][4];
#pragma unroll
    for (int nd = 0; nd < 8; nd++)
#pragma unroll
        for (int r = 0; r < 4; r++) o[nd][r] = 0.f;

    const float wd = w_disc[h];
    const int row0 = t0 + w * 16 + g;
    const int row1 = row0 + 8;

    for (int s0 = 0; s0 < t0 + 128; s0 += 64) {
        // ---- Stage K [key][72] half and V [dim][key] half ----
        const float* kb = ka + ((size_t)bh * TT + s0) * HD;
        const float* vb = qkv + (size_t)(b * TT + s0) * (3 * CC) + 2 * CC + h * HD;
#pragma unroll
        for (int it = 0; it < 4; it++) {
            int i = tid + it * 256;      // 64 rows x 16 float4
            int row = i >> 4, c4 = i & 15;
            float4 kv = *(const float4*)(kb + row * HD + c4 * 4);
            *(uint2*)&s_k[row * LDQ + c4 * 4] =
                make_uint2(f22h2(kv.x, kv.y), f22h2(kv.z, kv.w));
            float4 vv = *(const float4*)(vb + (size_t)row * (3 * CC) + c4 * 4);
            s_v[(c4 * 4 + 0) * LDQ + row] = __float2half(vv.x);
            s_v[(c4 * 4 + 1) * LDQ + row] = __float2half(vv.y);
            s_v[(c4 * 4 + 2) * LDQ + row] = __float2half(vv.z);
            s_v[(c4 * 4 + 3) * LDQ + row] = __float2half(vv.w);
        }
        if (tid < 64) s_b[tid] = wd * d_bias[h * TT + s0 + tid];
        __syncthreads();

        // ---- QK^T (fp16): S[16 rows][64 keys] per warp ----
        float sa[8][4];
#pragma unroll
        for (int ni = 0; ni < 8; ni++)
#pragma unroll
            for (int r = 0; r < 4; r++) sa[ni][r] = 0.f;

#pragma unroll
        for (int kc = 0; kc < 4; kc++) {
            unsigned bfr[8][2];
#pragma unroll
            for (int ni = 0; ni < 8; ni++) {
                const __half* p = &s_k[(ni * 8 + g) * LDQ + kc * 16 + 2 * q];
                bfr[ni][0] = *(const unsigned*)(p);
                bfr[ni][1] = *(const unsigned*)(p + 8);
            }
#pragma unroll
            for (int ni = 0; ni < 8; ni++)
                mma_f16(sa[ni][0], sa[ni][1], sa[ni][2], sa[ni][3],
                        qf[kc][0], qf[kc][1], qf[kc][2], qf[kc][3],
                        bfr[ni][0], bfr[ni][1]);
        }

        // ---- bias + causal mask + online softmax ----
        float mx0 = -1e30f, mx1 = -1e30f;
#pragma unroll
        for (int ni = 0; ni < 8; ni++) {
            int c = s0 + ni * 8 + 2 * q;
            float b0 = s_b[ni * 8 + 2 * q];
            float b1 = s_b[ni * 8 + 2 * q + 1];
            sa[ni][0] = (c     <= row0) ? sa[ni][0] + b0 : -1e30f;
            sa[ni][1] = (c + 1 <= row0) ? sa[ni][1] + b1 : -1e30f;
            sa[ni][2] = (c     <= row1) ? sa[ni][2] + b0 : -1e30f;
            sa[ni][3] = (c + 1 <= row1) ? sa[ni][3] + b1 : -1e30f;
            mx0 = fmaxf(mx0, fmaxf(sa[ni][0], sa[ni][1]));
            mx1 = fmaxf(mx1, fmaxf(sa[ni][2], sa[ni][3]));
        }
        mx0 = fmaxf(mx0, __shfl_xor_sync(0xffffffffu, mx0, 1));
        mx0 = fmaxf(mx0, __shfl_xor_sync(0xffffffffu, mx0, 2));
        mx1 = fmaxf(mx1, __shfl_xor_sync(0xffffffffu, mx1, 1));
        mx1 = fmaxf(mx1, __shfl_xor_sync(0xffffffffu, mx1, 2));

        float m0n = fmaxf(m0, mx0);
        float m1n = fmaxf(m1, mx1);
        float cr0 = __expf(m0 - m0n);
        float cr1 = __expf(m1 - m1n);

        unsigned ph0[8], ph1[8];
        float rs0 = 0.f, rs1 = 0.f;
#pragma unroll
        for (int ni = 0; ni < 8; ni++) {
            float p00 = __expf(sa[ni][0] - m0n);
            float p01 = __expf(sa[ni][1] - m0n);
            float p10 = __expf(sa[ni][2] - m1n);
            float p11 = __expf(sa[ni][3] - m1n);
            rs0 += p00 + p01;
            rs1 += p10 + p11;
            ph0[ni] = f22h2(p00, p01);
            ph1[ni] = f22h2(p10, p11);
        }
        rs0 += __shfl_xor_sync(0xffffffffu, rs0, 1);
        rs0 += __shfl_xor_sync(0xffffffffu, rs0, 2);
        rs1 += __shfl_xor_sync(0xffffffffu, rs1, 1);
        rs1 += __shfl_xor_sync(0xffffffffu, rs1, 2);

        l0 = l0 * cr0 + rs0;
        l1 = l1 * cr1 + rs1;
        m0 = m0n;
        m1 = m1n;
#pragma unroll
        for (int nd = 0; nd < 8; nd++) {
            o[nd][0] *= cr0; o[nd][1] *= cr0;
            o[nd][2] *= cr1; o[nd][3] *= cr1;
        }

        // ---- P * V (fp16): O[16 rows][64 dims] ----
#pragma unroll
        for (int kc = 0; kc < 4; kc++) {
            unsigned a0 = ph0[2 * kc];
            unsigned a1 = ph1[2 * kc];
            unsigned a2 = ph0[2 * kc + 1];
            unsigned a3 = ph1[2 * kc + 1];
#pragma unroll
            for (int nd = 0; nd < 8; nd++) {
                const __half* vp = &s_v[(nd * 8 + g) * LDQ + kc * 16 + 2 * q];
                unsigned b0 = *(const unsigned*)(vp);
                unsigned b1 = *(const unsigned*)(vp + 8);
                mma_f16(o[nd][0], o[nd][1], o[nd][2], o[nd][3],
                        a0, a1, a2, a3, b0, b1);
            }
        }
        __syncthreads();   // done reading K/V before next tile's staging
    }

    // ---- Epilogue: normalize and write (B,T,H,64) ----
    const float i0 = 1.f / l0;
    const float i1 = 1.f / l1;
    float* ob0 = ao + ((size_t)(b * TT + row0) * HH + h) * HD;
    float* ob1 = ao + ((size_t)(b * TT + row1) * HH + h) * HD;
#pragma unroll
    for (int nd = 0; nd < 8; nd++) {
        *(float2*)(ob0 + nd * 8 + 2 * q) = make_float2(o[nd][0] * i0, o[nd][1] * i0);
        *(float2*)(ob1 + nd * 8 + 2 * q) = make_float2(o[nd][2] * i1, o[nd][3] * i1);
    }
}

// ---------------------------------------------------------------------------
// Launch
// ---------------------------------------------------------------------------
extern "C" void kernel_launch(void* const* d_in, const int* in_sizes, int n_in,
                              void* d_out, int out_size)
{
    const float* x       = (const float*)d_in[0];
    const float* Wqkv    = (const float*)d_in[1];
    const float* Wproj   = (const float*)d_in[2];
    const float* W_recip = (const float*)d_in[3];
    const float* w_std   = (const float*)d_in[4];
    const float* w_rec   = (const float*)d_in[5];
    const float* w_disc  = (const float*)d_in[6];
    const float* d_bias  = (const float*)d_in[7];
    float* out = (float*)d_out;

    float *p_qkv, *p_qa, *p_ka, *p_ao;
    cudaGetSymbolAddress((void**)&p_qkv, g_qkv);
    cudaGetSymbolAddress((void**)&p_qa, g_qa);
    cudaGetSymbolAddress((void**)&p_ka, g_ka);
    cudaGetSymbolAddress((void**)&p_ao, g_ao);

    const int M = BB * TT;   // 4096

    // 1) qkv = x @ Wqkv^T
    gemm_nt_f16<<<dim3((3 * CC) / HBN, M / HBM), 256>>>(x, Wqkv, p_qkv, M, 3 * CC, CC);

    // 2) cross augmentation
    augment_kernel<<<BB * HH * TT / 4, 256>>>(p_qkv, p_qa, p_ka, W_recip, w_std, w_rec);

    // 3) fp16 tensor-core causal flash attention with key bias
    flash_mma<<<dim3(TT / 128, BB * HH), 256>>>(
        p_qa, p_ka, p_qkv, d_bias, w_disc, p_ao);

    // 4) out = ao @ Wproj^T
    gemm_nt_f16<<<dim3(CC / HBN, M / HBM), 256>>>(p_ao, Wproj, out, M, CC, CC);
}

// round 7
// speedup vs baseline: 8.0888x; 1.1888x over previous
#include <cuda_runtime.h>
#include <cuda_fp16.h>
#include <math.h>

// Problem constants (fixed shapes)
#define BB 2
#define TT 2048
#define CC 1024
#define HH 16
#define HD 64
#define RR 8
#define DSTD 56

// Scratch (static device globals — no allocation)
__device__ __half g_xh[(size_t)BB * TT * CC];          // x in half       8 MB
__device__ __half g_wqkvh[(size_t)3 * CC * CC];        // Wqkv in half    6 MB
__device__ __half g_wprojh[(size_t)CC * CC];           // Wproj in half   2 MB
__device__ __half g_qkvh[(size_t)BB * TT * 3 * CC];    // qkv (B,T,3C)   24 MB
__device__ __half g_qah[(size_t)BB * HH * TT * HD];    // q_aug * 1/8     8 MB
__device__ __half g_kah[(size_t)BB * HH * TT * HD];    // k_aug           8 MB
__device__ __half g_aoh[(size_t)BB * TT * CC];         // attn out        8 MB

__device__ __forceinline__ unsigned f22h2(float a, float b) {
    __half2 h = __floats2half2_rn(a, b);
    return *reinterpret_cast<unsigned*>(&h);
}

__device__ __forceinline__ void mma_f16(float& c0, float& c1, float& c2, float& c3,
                                        unsigned a0, unsigned a1, unsigned a2, unsigned a3,
                                        unsigned b0, unsigned b1) {
    asm volatile(
        "mma.sync.aligned.m16n8k16.row.col.f32.f16.f16.f32 "
        "{%0,%1,%2,%3}, {%4,%5,%6,%7}, {%8,%9}, {%0,%1,%2,%3};"
        : "+f"(c0), "+f"(c1), "+f"(c2), "+f"(c3)
        : "r"(a0), "r"(a1), "r"(a2), "r"(a3), "r"(b0), "r"(b1));
}

__device__ __forceinline__ void cp_async16(void* smem, const void* gmem) {
    unsigned s = (unsigned)__cvta_generic_to_shared(smem);
    asm volatile("cp.async.cg.shared.global [%0], [%1], 16;" :: "r"(s), "l"(gmem));
}
__device__ __forceinline__ void cp_commit() {
    asm volatile("cp.async.commit_group;");
}
__device__ __forceinline__ void cp_wait0() {
    asm volatile("cp.async.wait_group 0;");
}
__device__ __forceinline__ void cp_wait1() {
    asm volatile("cp.async.wait_group 1;");
}

// ---------------------------------------------------------------------------
// float -> half convert (n % 8 == 0)
// ---------------------------------------------------------------------------
__global__ __launch_bounds__(256) void f2h_kernel(
    const float* __restrict__ in, __half* __restrict__ out, int n)
{
    int i = (blockIdx.x * 256 + threadIdx.x) * 8;
    if (i < n) {
        float4 a = *(const float4*)(in + i);
        float4 b = *(const float4*)(in + i + 4);
        uint4 r;
        r.x = f22h2(a.x, a.y); r.y = f22h2(a.z, a.w);
        r.z = f22h2(b.x, b.y); r.w = f22h2(b.z, b.w);
        *(uint4*)(out + i) = r;
    }
}

// ---------------------------------------------------------------------------
// FP16 GEMM (NT), cp.async double-buffered: C[m,n] = sum_k A[m,k]*B[n,k]
// A:(M,K) half, B:(N,K) half. 128x128x32 tile, 256 thr = 8 warps (2m x 4n).
// smem [row][40 halves] -> conflict-free half2 fragment loads.
// ---------------------------------------------------------------------------
#define HBM 128
#define HBN 128
#define HBK 32
#define LDH 40

template <typename OutT>
__global__ __launch_bounds__(256, 2) void gemm_nt_h(
    const __half* __restrict__ A, const __half* __restrict__ B,
    OutT* __restrict__ C, int M, int N, int K)
{
    __shared__ __align__(16) __half sA[2][HBM * LDH];
    __shared__ __align__(16) __half sB[2][HBN * LDH];

    const int bm = blockIdx.y * HBM;
    const int bn = blockIdx.x * HBN;
    const int tid = threadIdx.x;
    const int wid = tid >> 5;
    const int lane = tid & 31;
    const int g = lane >> 2;
    const int q = lane & 3;
    const int wm = (wid >> 2) * 64;
    const int wn = (wid & 3) * 32;

    float acc[4][4][4];
#pragma unroll
    for (int i = 0; i < 4; i++)
#pragma unroll
        for (int j = 0; j < 4; j++)
#pragma unroll
            for (int r = 0; r < 4; r++) acc[i][j][r] = 0.f;

    const int nk = K / HBK;

    // stage tile k0 into buffer buf (128 rows x 32 halves = 4 x 16B per row)
    auto stage = [&](int buf, int koff) {
#pragma unroll
        for (int it = 0; it < 2; it++) {
            int f = tid + it * 256;        // 0..511
            int row = f >> 2, c = f & 3;
            cp_async16(&sA[buf][row * LDH + c * 8],
                       A + (size_t)(bm + row) * K + koff + c * 8);
            cp_async16(&sB[buf][row * LDH + c * 8],
                       B + (size_t)(bn + row) * K + koff + c * 8);
        }
        cp_commit();
    };

    stage(0, 0);

    for (int k0 = 0; k0 < nk; k0++) {
        const int cur = k0 & 1;
        const bool more = (k0 + 1 < nk);
        if (more) stage(cur ^ 1, (k0 + 1) * HBK);
        if (more) cp_wait1(); else cp_wait0();
        __syncthreads();

#pragma unroll
        for (int kc = 0; kc < 2; kc++) {
            unsigned af[4][4];
#pragma unroll
            for (int mi = 0; mi < 4; mi++) {
                const __half* p = &sA[cur][(wm + mi * 16 + g) * LDH + kc * 16 + 2 * q];
                af[mi][0] = *(const unsigned*)(p);
                af[mi][1] = *(const unsigned*)(p + 8 * LDH);
                af[mi][2] = *(const unsigned*)(p + 8);
                af[mi][3] = *(const unsigned*)(p + 8 * LDH + 8);
            }
            unsigned bf[4][2];
#pragma unroll
            for (int ni = 0; ni < 4; ni++) {
                const __half* p = &sB[cur][(wn + ni * 8 + g) * LDH + kc * 16 + 2 * q];
                bf[ni][0] = *(const unsigned*)(p);
                bf[ni][1] = *(const unsigned*)(p + 8);
            }
#pragma unroll
            for (int mi = 0; mi < 4; mi++)
#pragma unroll
                for (int ni = 0; ni < 4; ni++)
                    mma_f16(acc[mi][ni][0], acc[mi][ni][1], acc[mi][ni][2], acc[mi][ni][3],
                            af[mi][0], af[mi][1], af[mi][2], af[mi][3],
                            bf[ni][0], bf[ni][1]);
        }
        __syncthreads();
    }

#pragma unroll
    for (int mi = 0; mi < 4; mi++) {
#pragma unroll
        for (int ni = 0; ni < 4; ni++) {
            int row = bm + wm + mi * 16 + g;
            int col = bn + wn + ni * 8 + q * 2;
            if (sizeof(OutT) == 4) {
                *(float2*)((float*)C + (size_t)row * N + col) =
                    make_float2(acc[mi][ni][0], acc[mi][ni][1]);
                *(float2*)((float*)C + (size_t)(row + 8) * N + col) =
                    make_float2(acc[mi][ni][2], acc[mi][ni][3]);
            } else {
                *(unsigned*)((__half*)C + (size_t)row * N + col) =
                    f22h2(acc[mi][ni][0], acc[mi][ni][1]);
                *(unsigned*)((__half*)C + (size_t)(row + 8) * N + col) =
                    f22h2(acc[mi][ni][2], acc[mi][ni][3]);
            }
        }
    }
}

// ---------------------------------------------------------------------------
// Augmentation (half in/out): 4 (b,h,t) rows per 256-thread block.
// qa is pre-scaled by 1/8 (exact power of two) so flash stages Q as a copy.
// ---------------------------------------------------------------------------
__global__ __launch_bounds__(256) void augment_kernel(
    const __half* __restrict__ qkv, __half* __restrict__ qa, __half* __restrict__ ka,
    const float* __restrict__ W_recip, const float* __restrict__ w_std,
    const float* __restrict__ w_rec)
{
    const int grp = threadIdx.x >> 6;
    const int d = threadIdx.x & 63;
    const int idx = blockIdx.x * 4 + grp;
    const int t = idx % TT;
    const int h = (idx / TT) % HH;
    const int b = idx / (TT * HH);

    const __half* base = qkv + (size_t)(b * TT + t) * (3 * CC);

    float qd = __half2float(base[h * HD + d]);
    float kd = __half2float(base[CC + h * HD + d]);

    __shared__ float sq[4][HD], sk[4][HD], qlow[4][RR], klow[4][RR];
    sq[grp][d] = qd;
    sk[grp][d] = kd;
    __syncthreads();

    if (d < RR) {
        float s = 0.f;
#pragma unroll
        for (int i = 0; i < HD; i++) s += sq[grp][i] * W_recip[i * RR + d];
        qlow[grp][d] = s;
    } else if (d < 2 * RR) {
        int r = d - RR;
        float s = 0.f;
#pragma unroll
        for (int i = 0; i < HD; i++) s += sk[grp][i] * W_recip[i * RR + r];
        klow[grp][r] = s;
    }
    __syncthreads();

    const float sws = sqrtf(w_std[h]);
    const float swr = sqrtf(w_rec[h]);
    float qav = (d < DSTD) ? sws * qd : swr * klow[grp][d - DSTD];
    float kav = (d < DSTD) ? sws * kd : swr * qlow[grp][d - DSTD];

    size_t o = ((size_t)idx) * HD + d;
    qa[o] = __float2half(qav * 0.125f);   // fold softmax scale (exact)
    ka[o] = __float2half(kav);
}

// ---------------------------------------------------------------------------
// FP16 tensor-core flash attention (causal) with per-head key bias.
// Grid: (T/128, B*H), 256 threads = 8 warps; warp handles 16 query rows.
// Q [128][72] staged once via cp.async; per tile K [key][72] via cp.async,
// V [dim][key] pad 72 manual transpose. All mma fp16, fp32 softmax/accum.
// ---------------------------------------------------------------------------
#define LDQ 72

__global__ __launch_bounds__(256) void flash_mma(
    const __half* __restrict__ qa, const __half* __restrict__ ka,
    const __half* __restrict__ qkv, const float* __restrict__ d_bias,
    const float* __restrict__ w_disc, __half* __restrict__ ao)
{
    __shared__ __align__(16) __half s_q[128 * LDQ];
    __shared__ __align__(16) __half s_k[64 * LDQ];
    __shared__ __align__(16) __half s_v[64 * LDQ];
    __shared__ float s_b[64];

    const int bh = blockIdx.y;
    const int b = bh >> 4;
    const int h = bh & 15;
    const int t0 = blockIdx.x * 128;
    const int tid = threadIdx.x;
    const int w = tid >> 5;
    const int lane = tid & 31;
    const int g = lane >> 2;
    const int q = lane & 3;

    // ---- Stage Q tile (pre-scaled in augment) via cp.async ----
    const __half* qbase = qa + ((size_t)bh * TT + t0) * HD;
#pragma unroll
    for (int it = 0; it < 4; it++) {
        int i = tid + it * 256;          // 0..1023 chunks (128 rows x 8)
        int row = i >> 3, c = i & 7;
        cp_async16(&s_q[row * LDQ + c * 8], qbase + row * HD + c * 8);
    }
    cp_commit();
    cp_wait0();
    __syncthreads();

    unsigned qf[4][4];
    {
        const int r0 = w * 16 + g;
#pragma unroll
        for (int kc = 0; kc < 4; kc++) {
            const __half* p = &s_q[r0 * LDQ + kc * 16 + 2 * q];
            qf[kc][0] = *(const unsigned*)(p);
            qf[kc][1] = *(const unsigned*)(p + 8 * LDQ);
            qf[kc][2] = *(const unsigned*)(p + 8);
            qf[kc][3] = *(const unsigned*)(p + 8 * LDQ + 8);
        }
    }

    float m0 = -1e30f, m1 = -1e30f, l0 = 0.f, l1 = 0.f;
    float o[8][4];
#pragma unroll
    for (int nd = 0; nd < 8; nd++)
#pragma unroll
        for (int r = 0; r < 4; r++) o[nd][r] = 0.f;

    const float wd = w_disc[h];
    const int row0 = t0 + w * 16 + g;
    const int row1 = row0 + 8;

    for (int s0 = 0; s0 < t0 + 128; s0 += 64) {
        // ---- Stage K via cp.async, V via manual transpose ----
        const __half* kb = ka + ((size_t)bh * TT + s0) * HD;
        const __half* vb = qkv + (size_t)(b * TT + s0) * (3 * CC) + 2 * CC + h * HD;
#pragma unroll
        for (int it = 0; it < 2; it++) {
            int i = tid + it * 256;      // 0..511 (64 rows x 8 chunks)
            int row = i >> 3, c = i & 7;
            cp_async16(&s_k[row * LDQ + c * 8], kb + row * HD + c * 8);
        }
        cp_commit();
#pragma unroll
        for (int it = 0; it < 2; it++) {
            int i = tid + it * 256;
            int row = i >> 3, c = i & 7;
            uint4 v8 = *(const uint4*)(vb + (size_t)row * (3 * CC) + c * 8);
            const __half* hp = (const __half*)&v8;
#pragma unroll
            for (int j = 0; j < 8; j++)
                s_v[(c * 8 + j) * LDQ + row] = hp[j];
        }
        if (tid < 64) s_b[tid] = wd * d_bias[h * TT + s0 + tid];
        cp_wait0();
        __syncthreads();

        // ---- QK^T (fp16): S[16 rows][64 keys] per warp ----
        float sa[8][4];
#pragma unroll
        for (int ni = 0; ni < 8; ni++)
#pragma unroll
            for (int r = 0; r < 4; r++) sa[ni][r] = 0.f;

#pragma unroll
        for (int kc = 0; kc < 4; kc++) {
            unsigned bfr[8][2];
#pragma unroll
            for (int ni = 0; ni < 8; ni++) {
                const __half* p = &s_k[(ni * 8 + g) * LDQ + kc * 16 + 2 * q];
                bfr[ni][0] = *(const unsigned*)(p);
                bfr[ni][1] = *(const unsigned*)(p + 8);
            }
#pragma unroll
            for (int ni = 0; ni < 8; ni++)
                mma_f16(sa[ni][0], sa[ni][1], sa[ni][2], sa[ni][3],
                        qf[kc][0], qf[kc][1], qf[kc][2], qf[kc][3],
                        bfr[ni][0], bfr[ni][1]);
        }

        // ---- bias + causal mask + online softmax ----
        float mx0 = -1e30f, mx1 = -1e30f;
#pragma unroll
        for (int ni = 0; ni < 8; ni++) {
            int c = s0 + ni * 8 + 2 * q;
            float b0 = s_b[ni * 8 + 2 * q];
            float b1 = s_b[ni * 8 + 2 * q + 1];
            sa[ni][0] = (c     <= row0) ? sa[ni][0] + b0 : -1e30f;
            sa[ni][1] = (c + 1 <= row0) ? sa[ni][1] + b1 : -1e30f;
            sa[ni][2] = (c     <= row1) ? sa[ni][2] + b0 : -1e30f;
            sa[ni][3] = (c + 1 <= row1) ? sa[ni][3] + b1 : -1e30f;
            mx0 = fmaxf(mx0, fmaxf(sa[ni][0], sa[ni][1]));
            mx1 = fmaxf(mx1, fmaxf(sa[ni][2], sa[ni][3]));
        }
        mx0 = fmaxf(mx0, __shfl_xor_sync(0xffffffffu, mx0, 1));
        mx0 = fmaxf(mx0, __shfl_xor_sync(0xffffffffu, mx0, 2));
        mx1 = fmaxf(mx1, __shfl_xor_sync(0xffffffffu, mx1, 1));
        mx1 = fmaxf(mx1, __shfl_xor_sync(0xffffffffu, mx1, 2));

        float m0n = fmaxf(m0, mx0);
        float m1n = fmaxf(m1, mx1);
        float cr0 = __expf(m0 - m0n);
        float cr1 = __expf(m1 - m1n);

        unsigned ph0[8], ph1[8];
        float rs0 = 0.f, rs1 = 0.f;
#pragma unroll
        for (int ni = 0; ni < 8; ni++) {
            float p00 = __expf(sa[ni][0] - m0n);
            float p01 = __expf(sa[ni][1] - m0n);
            float p10 = __expf(sa[ni][2] - m1n);
            float p11 = __expf(sa[ni][3] - m1n);
            rs0 += p00 + p01;
            rs1 += p10 + p11;
            ph0[ni] = f22h2(p00, p01);
            ph1[ni] = f22h2(p10, p11);
        }
        rs0 += __shfl_xor_sync(0xffffffffu, rs0, 1);
        rs0 += __shfl_xor_sync(0xffffffffu, rs0, 2);
        rs1 += __shfl_xor_sync(0xffffffffu, rs1, 1);
        rs1 += __shfl_xor_sync(0xffffffffu, rs1, 2);

        l0 = l0 * cr0 + rs0;
        l1 = l1 * cr1 + rs1;
        m0 = m0n;
        m1 = m1n;
#pragma unroll
        for (int nd = 0; nd < 8; nd++) {
            o[nd][0] *= cr0; o[nd][1] *= cr0;
            o[nd][2] *= cr1; o[nd][3] *= cr1;
        }

        // ---- P * V (fp16): O[16 rows][64 dims] ----
#pragma unroll
        for (int kc = 0; kc < 4; kc++) {
            unsigned a0 = ph0[2 * kc];
            unsigned a1 = ph1[2 * kc];
            unsigned a2 = ph0[2 * kc + 1];
            unsigned a3 = ph1[2 * kc + 1];
#pragma unroll
            for (int nd = 0; nd < 8; nd++) {
                const __half* vp = &s_v[(nd * 8 + g) * LDQ + kc * 16 + 2 * q];
                unsigned b0 = *(const unsigned*)(vp);
                unsigned b1 = *(const unsigned*)(vp + 8);
                mma_f16(o[nd][0], o[nd][1], o[nd][2], o[nd][3],
                        a0, a1, a2, a3, b0, b1);
            }
        }
        __syncthreads();   // done reading K/V before next tile's staging
    }

    // ---- Epilogue: normalize and write half (B,T,H,64) ----
    const float i0 = 1.f / l0;
    const float i1 = 1.f / l1;
    __half* ob0 = ao + ((size_t)(b * TT + row0) * HH + h) * HD;
    __half* ob1 = ao + ((size_t)(b * TT + row1) * HH + h) * HD;
#pragma unroll
    for (int nd = 0; nd < 8; nd++) {
        *(unsigned*)(ob0 + nd * 8 + 2 * q) = f22h2(o[nd][0] * i0, o[nd][1] * i0);
        *(unsigned*)(ob1 + nd * 8 + 2 * q) = f22h2(o[nd][2] * i1, o[nd][3] * i1);
    }
}

// ---------------------------------------------------------------------------
// Launch
// ---------------------------------------------------------------------------
extern "C" void kernel_launch(void* const* d_in, const int* in_sizes, int n_in,
                              void* d_out, int out_size)
{
    const float* x       = (const float*)d_in[0];
    const float* Wqkv    = (const float*)d_in[1];
    const float* Wproj   = (const float*)d_in[2];
    const float* W_recip = (const float*)d_in[3];
    const float* w_std   = (const float*)d_in[4];
    const float* w_rec   = (const float*)d_in[5];
    const float* w_disc  = (const float*)d_in[6];
    const float* d_bias  = (const float*)d_in[7];
    float* out = (float*)d_out;

    __half *p_xh, *p_wqkvh, *p_wprojh, *p_qkvh, *p_qah, *p_kah, *p_aoh;
    cudaGetSymbolAddress((void**)&p_xh, g_xh);
    cudaGetSymbolAddress((void**)&p_wqkvh, g_wqkvh);
    cudaGetSymbolAddress((void**)&p_wprojh, g_wprojh);
    cudaGetSymbolAddress((void**)&p_qkvh, g_qkvh);
    cudaGetSymbolAddress((void**)&p_qah, g_qah);
    cudaGetSymbolAddress((void**)&p_kah, g_kah);
    cudaGetSymbolAddress((void**)&p_aoh, g_aoh);

    const int M = BB * TT;       // 4096
    const int NX = BB * TT * CC; // 4194304
    const int NW1 = 3 * CC * CC; // 3145728
    const int NW2 = CC * CC;     // 1048576

    // 0) fp32 -> fp16 conversions
    f2h_kernel<<<(NX / 8 + 255) / 256, 256>>>(x, p_xh, NX);
    f2h_kernel<<<(NW1 / 8 + 255) / 256, 256>>>(Wqkv, p_wqkvh, NW1);
    f2h_kernel<<<(NW2 / 8 + 255) / 256, 256>>>(Wproj, p_wprojh, NW2);

    // 1) qkv = x @ Wqkv^T  (half out)
    gemm_nt_h<__half><<<dim3((3 * CC) / HBN, M / HBM), 256>>>(
        p_xh, p_wqkvh, p_qkvh, M, 3 * CC, CC);

    // 2) cross augmentation (qa pre-scaled by 1/8)
    augment_kernel<<<BB * HH * TT / 4, 256>>>(p_qkvh, p_qah, p_kah,
                                              W_recip, w_std, w_rec);

    // 3) fp16 causal flash attention with key bias (half out)
    flash_mma<<<dim3(TT / 128, BB * HH), 256>>>(
        p_qah, p_kah, p_qkvh, d_bias, w_disc, p_aoh);

    // 4) out = ao @ Wproj^T  (fp32 out)
    gemm_nt_h<float><<<dim3(CC / HBN, M / HBM), 256>>>(
        p_aoh, p_wprojh, out, M, CC, CC);
}

// round 8
// speedup vs baseline: 10.1559x; 1.2555x over previous
#include <cuda_runtime.h>
#include <cuda_fp16.h>
#include <math.h>

// Problem constants (fixed shapes)
#define BB 2
#define TT 2048
#define CC 1024
#define HH 16
#define HD 64
#define RR 8
#define DSTD 56

// Scratch (static device globals — no allocation)
__device__ __half g_xh[(size_t)BB * TT * CC];
__device__ __half g_wqkvh[(size_t)3 * CC * CC];
__device__ __half g_wprojh[(size_t)CC * CC];
__device__ __half g_qkvh[(size_t)BB * TT * 3 * CC];
__device__ __half g_qah[(size_t)BB * HH * TT * HD];
__device__ __half g_kah[(size_t)BB * HH * TT * HD];
__device__ __half g_aoh[(size_t)BB * TT * CC];

__device__ __forceinline__ unsigned f22h2(float a, float b) {
    __half2 h = __floats2half2_rn(a, b);
    return *reinterpret_cast<unsigned*>(&h);
}

__device__ __forceinline__ void mma_f16(float& c0, float& c1, float& c2, float& c3,
                                        unsigned a0, unsigned a1, unsigned a2, unsigned a3,
                                        unsigned b0, unsigned b1) {
    asm volatile(
        "mma.sync.aligned.m16n8k16.row.col.f32.f16.f16.f32 "
        "{%0,%1,%2,%3}, {%4,%5,%6,%7}, {%8,%9}, {%0,%1,%2,%3};"
        : "+f"(c0), "+f"(c1), "+f"(c2), "+f"(c3)
        : "r"(a0), "r"(a1), "r"(a2), "r"(a3), "r"(b0), "r"(b1));
}

__device__ __forceinline__ void ldm_x4(unsigned r[4], const __half* p) {
    unsigned a = (unsigned)__cvta_generic_to_shared(p);
    asm volatile("ldmatrix.sync.aligned.m8n8.x4.shared.b16 {%0,%1,%2,%3}, [%4];"
                 : "=r"(r[0]), "=r"(r[1]), "=r"(r[2]), "=r"(r[3]) : "r"(a));
}
__device__ __forceinline__ void ldm_x4_t(unsigned r[4], const __half* p) {
    unsigned a = (unsigned)__cvta_generic_to_shared(p);
    asm volatile("ldmatrix.sync.aligned.m8n8.x4.trans.shared.b16 {%0,%1,%2,%3}, [%4];"
                 : "=r"(r[0]), "=r"(r[1]), "=r"(r[2]), "=r"(r[3]) : "r"(a));
}

__device__ __forceinline__ void cp_async16(void* smem, const void* gmem) {
    unsigned s = (unsigned)__cvta_generic_to_shared(smem);
    asm volatile("cp.async.cg.shared.global [%0], [%1], 16;" :: "r"(s), "l"(gmem));
}
__device__ __forceinline__ void cp_commit() { asm volatile("cp.async.commit_group;"); }
__device__ __forceinline__ void cp_wait0() { asm volatile("cp.async.wait_group 0;"); }
__device__ __forceinline__ void cp_wait1() { asm volatile("cp.async.wait_group 1;"); }

// ---------------------------------------------------------------------------
// float -> half convert (n % 8 == 0)
// ---------------------------------------------------------------------------
__global__ __launch_bounds__(256) void f2h_kernel(
    const float* __restrict__ in, __half* __restrict__ out, int n)
{
    int i = (blockIdx.x * 256 + threadIdx.x) * 8;
    if (i < n) {
        float4 a = *(const float4*)(in + i);
        float4 b = *(const float4*)(in + i + 4);
        uint4 r;
        r.x = f22h2(a.x, a.y); r.y = f22h2(a.z, a.w);
        r.z = f22h2(b.x, b.y); r.w = f22h2(b.z, b.w);
        *(uint4*)(out + i) = r;
    }
}

// ---------------------------------------------------------------------------
// FP16 GEMM (NT), 3-stage cp.async + ldmatrix: C[m,n] = sum_k A[m,k]*B[n,k]
// 128x128x32 tile, 256 thr = 8 warps (2m x 4n), warp tile 64x32.
// ---------------------------------------------------------------------------
#define HBM 128
#define HBN 128
#define HBK 32
#define LDH 40

template <typename OutT>
__global__ __launch_bounds__(256, 2) void gemm_nt_h(
    const __half* __restrict__ A, const __half* __restrict__ B,
    OutT* __restrict__ C, int M, int N, int K)
{
    __shared__ __align__(16) __half sA[3][HBM * LDH];
    __shared__ __align__(16) __half sB[3][HBN * LDH];

    const int bm = blockIdx.y * HBM;
    const int bn = blockIdx.x * HBN;
    const int tid = threadIdx.x;
    const int wid = tid >> 5;
    const int lane = tid & 31;
    const int g = lane >> 2;
    const int q = lane & 3;
    const int wm = (wid >> 2) * 64;
    const int wn = (wid & 3) * 32;

    // ldmatrix per-lane offsets
    const int l8 = lane & 7;
    const int sel = lane >> 3;
    const int arow = l8 + ((sel & 1) ? 8 : 0);
    const int acol = (sel & 2) ? 8 : 0;
    const int brow = l8 + ((sel & 2) ? 8 : 0);
    const int bcol = (sel & 1) ? 8 : 0;

    float acc[4][4][4];
#pragma unroll
    for (int i = 0; i < 4; i++)
#pragma unroll
        for (int j = 0; j < 4; j++)
#pragma unroll
            for (int r = 0; r < 4; r++) acc[i][j][r] = 0.f;

    const int nk = K / HBK;

    auto stage = [&](int buf, int koff) {
#pragma unroll
        for (int it = 0; it < 2; it++) {
            int f = tid + it * 256;
            int row = f >> 2, c = f & 3;
            cp_async16(&sA[buf][row * LDH + c * 8],
                       A + (size_t)(bm + row) * K + koff + c * 8);
            cp_async16(&sB[buf][row * LDH + c * 8],
                       B + (size_t)(bn + row) * K + koff + c * 8);
        }
        cp_commit();
    };

    stage(0, 0);
    stage(1, HBK);

    for (int k0 = 0; k0 < nk; k0++) {
        const int cur = k0 % 3;
        if (k0 + 1 < nk) cp_wait1(); else cp_wait0();
        __syncthreads();
        if (k0 + 2 < nk) stage((k0 + 2) % 3, (k0 + 2) * HBK);

#pragma unroll
        for (int kc = 0; kc < 2; kc++) {
            unsigned af[4][4];
#pragma unroll
            for (int mi = 0; mi < 4; mi++)
                ldm_x4(af[mi], &sA[cur][(wm + mi * 16 + arow) * LDH + kc * 16 + acol]);
            unsigned bf[2][4];
#pragma unroll
            for (int nj = 0; nj < 2; nj++)
                ldm_x4(bf[nj], &sB[cur][(wn + nj * 16 + brow) * LDH + kc * 16 + bcol]);
#pragma unroll
            for (int mi = 0; mi < 4; mi++)
#pragma unroll
                for (int ni = 0; ni < 4; ni++)
                    mma_f16(acc[mi][ni][0], acc[mi][ni][1], acc[mi][ni][2], acc[mi][ni][3],
                            af[mi][0], af[mi][1], af[mi][2], af[mi][3],
                            bf[ni >> 1][(ni & 1) * 2], bf[ni >> 1][(ni & 1) * 2 + 1]);
        }
        // no bottom sync: next iteration's top barrier protects buffer reuse
    }

#pragma unroll
    for (int mi = 0; mi < 4; mi++) {
#pragma unroll
        for (int ni = 0; ni < 4; ni++) {
            int row = bm + wm + mi * 16 + g;
            int col = bn + wn + ni * 8 + q * 2;
            if (sizeof(OutT) == 4) {
                *(float2*)((float*)C + (size_t)row * N + col) =
                    make_float2(acc[mi][ni][0], acc[mi][ni][1]);
                *(float2*)((float*)C + (size_t)(row + 8) * N + col) =
                    make_float2(acc[mi][ni][2], acc[mi][ni][3]);
            } else {
                *(unsigned*)((__half*)C + (size_t)row * N + col) =
                    f22h2(acc[mi][ni][0], acc[mi][ni][1]);
                *(unsigned*)((__half*)C + (size_t)(row + 8) * N + col) =
                    f22h2(acc[mi][ni][2], acc[mi][ni][3]);
            }
        }
    }
}

// ---------------------------------------------------------------------------
// Augmentation (half in/out); qa pre-scaled by 1/8 (exact).
// ---------------------------------------------------------------------------
__global__ __launch_bounds__(256) void augment_kernel(
    const __half* __restrict__ qkv, __half* __restrict__ qa, __half* __restrict__ ka,
    const float* __restrict__ W_recip, const float* __restrict__ w_std,
    const float* __restrict__ w_rec)
{
    const int grp = threadIdx.x >> 6;
    const int d = threadIdx.x & 63;
    const int idx = blockIdx.x * 4 + grp;
    const int t = idx % TT;
    const int h = (idx / TT) % HH;
    const int b = idx / (TT * HH);

    const __half* base = qkv + (size_t)(b * TT + t) * (3 * CC);

    float qd = __half2float(base[h * HD + d]);
    float kd = __half2float(base[CC + h * HD + d]);

    __shared__ float sq[4][HD], sk[4][HD], qlow[4][RR], klow[4][RR];
    sq[grp][d] = qd;
    sk[grp][d] = kd;
    __syncthreads();

    if (d < RR) {
        float s = 0.f;
#pragma unroll
        for (int i = 0; i < HD; i++) s += sq[grp][i] * W_recip[i * RR + d];
        qlow[grp][d] = s;
    } else if (d < 2 * RR) {
        int r = d - RR;
        float s = 0.f;
#pragma unroll
        for (int i = 0; i < HD; i++) s += sk[grp][i] * W_recip[i * RR + r];
        klow[grp][r] = s;
    }
    __syncthreads();

    const float sws = sqrtf(w_std[h]);
    const float swr = sqrtf(w_rec[h]);
    float qav = (d < DSTD) ? sws * qd : swr * klow[grp][d - DSTD];
    float kav = (d < DSTD) ? sws * kd : swr * qlow[grp][d - DSTD];

    size_t o = ((size_t)idx) * HD + d;
    qa[o] = __float2half(qav * 0.125f);
    ka[o] = __float2half(kav);
}

// ---------------------------------------------------------------------------
// FP16 flash attention (causal) with per-head key bias.
// Grid: (T/128, B*H), 256 threads = 8 warps; warp handles 16 query rows.
// K and V both staged [key][LDQ] via cp.async (double-buffered); fragments
// via ldmatrix (V via ldmatrix.trans). fp32 softmax/accum.
// ---------------------------------------------------------------------------
#define LDQ 72

__global__ __launch_bounds__(256) void flash_mma(
    const __half* __restrict__ qa, const __half* __restrict__ ka,
    const __half* __restrict__ qkv, const float* __restrict__ d_bias,
    const float* __restrict__ w_disc, __half* __restrict__ ao)
{
    __shared__ __align__(16) __half s_q[128 * LDQ];
    __shared__ __align__(16) __half s_k[2][64 * LDQ];
    __shared__ __align__(16) __half s_v[2][64 * LDQ];
    __shared__ float s_b[2][64];

    const int bh = blockIdx.y;
    const int b = bh >> 4;
    const int h = bh & 15;
    const int t0 = blockIdx.x * 128;
    const int tid = threadIdx.x;
    const int w = tid >> 5;
    const int lane = tid & 31;
    const int g = lane >> 2;
    const int q = lane & 3;

    const int l8 = lane & 7;
    const int sel = lane >> 3;
    const int arow = l8 + ((sel & 1) ? 8 : 0);   // A (Q) frags
    const int acol = (sel & 2) ? 8 : 0;
    const int brow = l8 + ((sel & 2) ? 8 : 0);   // B (K) frags
    const int bcol = (sel & 1) ? 8 : 0;
    const int vrow = l8 + ((sel & 1) ? 8 : 0);   // V trans frags (key offset)
    const int vcol = (sel & 2) ? 8 : 0;          // (dim offset)

    const float wd = w_disc[h];

    // ---- Stage Q (group 0) ----
    const __half* qbase = qa + ((size_t)bh * TT + t0) * HD;
#pragma unroll
    for (int it = 0; it < 4; it++) {
        int i = tid + it * 256;
        int row = i >> 3, c = i & 7;
        cp_async16(&s_q[row * LDQ + c * 8], qbase + row * HD + c * 8);
    }
    cp_commit();

    auto stage_kv = [&](int i) {
        int buf = i & 1;
        int s0 = i * 64;
        const __half* kb = ka + ((size_t)bh * TT + s0) * HD;
        const __half* vb = qkv + (size_t)(b * TT + s0) * (3 * CC) + 2 * CC + h * HD;
#pragma unroll
        for (int it = 0; it < 2; it++) {
            int f = tid + it * 256;       // 64 rows x 8 chunks
            int row = f >> 3, c = f & 7;
            cp_async16(&s_k[buf][row * LDQ + c * 8], kb + row * HD + c * 8);
            cp_async16(&s_v[buf][row * LDQ + c * 8],
                       vb + (size_t)row * (3 * CC) + c * 8);
        }
        if (tid < 64) s_b[buf][tid] = wd * d_bias[h * TT + s0 + tid];
        cp_commit();
    };

    stage_kv(0);          // group 1
    cp_wait1();           // Q (group 0) done
    __syncthreads();

    unsigned qf[4][4];
#pragma unroll
    for (int kc = 0; kc < 4; kc++)
        ldm_x4(qf[kc], &s_q[(w * 16 + arow) * LDQ + kc * 16 + acol]);

    float m0 = -1e30f, m1 = -1e30f, l0 = 0.f, l1 = 0.f;
    float o[8][4];
#pragma unroll
    for (int nd = 0; nd < 8; nd++)
#pragma unroll
        for (int r = 0; r < 4; r++) o[nd][r] = 0.f;

    const int row0 = t0 + w * 16 + g;
    const int row1 = row0 + 8;
    const int nt = blockIdx.x * 2 + 2;   // number of 64-key tiles

    for (int i = 0; i < nt; i++) {
        const int cur = i & 1;
        const int s0 = i * 64;
        cp_wait0();
        __syncthreads();
        if (i + 1 < nt) stage_kv(i + 1);   // overlaps this tile's compute

        // ---- QK^T ----
        float sa[8][4];
#pragma unroll
        for (int ni = 0; ni < 8; ni++)
#pragma unroll
            for (int r = 0; r < 4; r++) sa[ni][r] = 0.f;

#pragma unroll
        for (int kc = 0; kc < 4; kc++) {
            unsigned bk[4][4];
#pragma unroll
            for (int nj = 0; nj < 4; nj++)
                ldm_x4(bk[nj], &s_k[cur][(nj * 16 + brow) * LDQ + kc * 16 + bcol]);
#pragma unroll
            for (int ni = 0; ni < 8; ni++)
                mma_f16(sa[ni][0], sa[ni][1], sa[ni][2], sa[ni][3],
                        qf[kc][0], qf[kc][1], qf[kc][2], qf[kc][3],
                        bk[ni >> 1][(ni & 1) * 2], bk[ni >> 1][(ni & 1) * 2 + 1]);
        }

        // ---- bias + causal mask + online softmax ----
        float mx0 = -1e30f, mx1 = -1e30f;
#pragma unroll
        for (int ni = 0; ni < 8; ni++) {
            int c = s0 + ni * 8 + 2 * q;
            float b0 = s_b[cur][ni * 8 + 2 * q];
            float b1 = s_b[cur][ni * 8 + 2 * q + 1];
            sa[ni][0] = (c     <= row0) ? sa[ni][0] + b0 : -1e30f;
            sa[ni][1] = (c + 1 <= row0) ? sa[ni][1] + b1 : -1e30f;
            sa[ni][2] = (c     <= row1) ? sa[ni][2] + b0 : -1e30f;
            sa[ni][3] = (c + 1 <= row1) ? sa[ni][3] + b1 : -1e30f;
            mx0 = fmaxf(mx0, fmaxf(sa[ni][0], sa[ni][1]));
            mx1 = fmaxf(mx1, fmaxf(sa[ni][2], sa[ni][3]));
        }
        mx0 = fmaxf(mx0, __shfl_xor_sync(0xffffffffu, mx0, 1));
        mx0 = fmaxf(mx0, __shfl_xor_sync(0xffffffffu, mx0, 2));
        mx1 = fmaxf(mx1, __shfl_xor_sync(0xffffffffu, mx1, 1));
        mx1 = fmaxf(mx1, __shfl_xor_sync(0xffffffffu, mx1, 2));

        float m0n = fmaxf(m0, mx0);
        float m1n = fmaxf(m1, mx1);
        float cr0 = __expf(m0 - m0n);
        float cr1 = __expf(m1 - m1n);

        unsigned ph0[8], ph1[8];
        float rs0 = 0.f, rs1 = 0.f;
#pragma unroll
        for (int ni = 0; ni < 8; ni++) {
            float p00 = __expf(sa[ni][0] - m0n);
            float p01 = __expf(sa[ni][1] - m0n);
            float p10 = __expf(sa[ni][2] - m1n);
            float p11 = __expf(sa[ni][3] - m1n);
            rs0 += p00 + p01;
            rs1 += p10 + p11;
            ph0[ni] = f22h2(p00, p01);
            ph1[ni] = f22h2(p10, p11);
        }
        rs0 += __shfl_xor_sync(0xffffffffu, rs0, 1);
        rs0 += __shfl_xor_sync(0xffffffffu, rs0, 2);
        rs1 += __shfl_xor_sync(0xffffffffu, rs1, 1);
        rs1 += __shfl_xor_sync(0xffffffffu, rs1, 2);

        l0 = l0 * cr0 + rs0;
        l1 = l1 * cr1 + rs1;
        m0 = m0n;
        m1 = m1n;
#pragma unroll
        for (int nd = 0; nd < 8; nd++) {
            o[nd][0] *= cr0; o[nd][1] *= cr0;
            o[nd][2] *= cr1; o[nd][3] *= cr1;
        }

        // ---- P * V (V frags via ldmatrix.trans from [key][dim]) ----
#pragma unroll
        for (int kc = 0; kc < 4; kc++) {
            unsigned a0 = ph0[2 * kc];
            unsigned a1 = ph1[2 * kc];
            unsigned a2 = ph0[2 * kc + 1];
            unsigned a3 = ph1[2 * kc + 1];
#pragma unroll
            for (int nj = 0; nj < 4; nj++) {
                unsigned bv[4];
                ldm_x4_t(bv, &s_v[cur][(kc * 16 + vrow) * LDQ + nj * 16 + vcol]);
                mma_f16(o[2 * nj][0], o[2 * nj][1], o[2 * nj][2], o[2 * nj][3],
                        a0, a1, a2, a3, bv[0], bv[1]);
                mma_f16(o[2 * nj + 1][0], o[2 * nj + 1][1], o[2 * nj + 1][2], o[2 * nj + 1][3],
                        a0, a1, a2, a3, bv[2], bv[3]);
            }
        }
        // no bottom sync: next iteration's top barrier protects buffer reuse
    }

    // ---- Epilogue: normalize and write half (B,T,H,64) ----
    const float i0 = 1.f / l0;
    const float i1 = 1.f / l1;
    __half* ob0 = ao + ((size_t)(b * TT + row0) * HH + h) * HD;
    __half* ob1 = ao + ((size_t)(b * TT + row1) * HH + h) * HD;
#pragma unroll
    for (int nd = 0; nd < 8; nd++) {
        *(unsigned*)(ob0 + nd * 8 + 2 * q) = f22h2(o[nd][0] * i0, o[nd][1] * i0);
        *(unsigned*)(ob1 + nd * 8 + 2 * q) = f22h2(o[nd][2] * i1, o[nd][3] * i1);
    }
}

// ---------------------------------------------------------------------------
// Launch
// ---------------------------------------------------------------------------
extern "C" void kernel_launch(void* const* d_in, const int* in_sizes, int n_in,
                              void* d_out, int out_size)
{
    const float* x       = (const float*)d_in[0];
    const float* Wqkv    = (const float*)d_in[1];
    const float* Wproj   = (const float*)d_in[2];
    const float* W_recip = (const float*)d_in[3];
    const float* w_std   = (const float*)d_in[4];
    const float* w_rec   = (const float*)d_in[5];
    const float* w_disc  = (const float*)d_in[6];
    const float* d_bias  = (const float*)d_in[7];
    float* out = (float*)d_out;

    __half *p_xh, *p_wqkvh, *p_wprojh, *p_qkvh, *p_qah, *p_kah, *p_aoh;
    cudaGetSymbolAddress((void**)&p_xh, g_xh);
    cudaGetSymbolAddress((void**)&p_wqkvh, g_wqkvh);
    cudaGetSymbolAddress((void**)&p_wprojh, g_wprojh);
    cudaGetSymbolAddress((void**)&p_qkvh, g_qkvh);
    cudaGetSymbolAddress((void**)&p_qah, g_qah);
    cudaGetSymbolAddress((void**)&p_kah, g_kah);
    cudaGetSymbolAddress((void**)&p_aoh, g_aoh);

    const int M = BB * TT;       // 4096
    const int NX = BB * TT * CC;
    const int NW1 = 3 * CC * CC;
    const int NW2 = CC * CC;

    // 0) fp32 -> fp16 conversions
    f2h_kernel<<<(NX / 8 + 255) / 256, 256>>>(x, p_xh, NX);
    f2h_kernel<<<(NW1 / 8 + 255) / 256, 256>>>(Wqkv, p_wqkvh, NW1);
    f2h_kernel<<<(NW2 / 8 + 255) / 256, 256>>>(Wproj, p_wprojh, NW2);

    // 1) qkv = x @ Wqkv^T  (half out)
    gemm_nt_h<__half><<<dim3((3 * CC) / HBN, M / HBM), 256>>>(
        p_xh, p_wqkvh, p_qkvh, M, 3 * CC, CC);

    // 2) cross augmentation (qa pre-scaled by 1/8)
    augment_kernel<<<BB * HH * TT / 4, 256>>>(p_qkvh, p_qah, p_kah,
                                              W_recip, w_std, w_rec);

    // 3) fp16 causal flash attention with key bias (half out)
    flash_mma<<<dim3(TT / 128, BB * HH), 256>>>(
        p_qah, p_kah, p_qkvh, d_bias, w_disc, p_aoh);

    // 4) out = ao @ Wproj^T  (fp32 out)
    gemm_nt_h<float><<<dim3(CC / HBN, M / HBM), 256>>>(
        p_aoh, p_wprojh, out, M, CC, CC);
}